// round 6
// baseline (speedup 1.0000x reference)
#include <cuda_runtime.h>
#include <cstdint>

#define MAX_N 50000

// ---------------- device scratch (no allocation allowed) -------------------
__device__ float  g_agg[(size_t)MAX_N * 256];     // [N][256] aggregation
__device__ int8_t g_w1q[2][2][65536];             // [dir][hi/lo][n*256+k]
__device__ int8_t g_w2q[2][2][65536];
__device__ float  g_w1s[2][256];                  // per-col scales
__device__ float  g_w2s[2][256];

// ---------------- small asm helpers ----------------------------------------
__device__ __forceinline__ uint32_t smem_u32(const void* p) {
    uint32_t a;
    asm("{ .reg .u64 t; cvta.to.shared.u64 t, %1; cvt.u32.u64 %0, t; }" : "=r"(a) : "l"(p));
    return a;
}
__device__ __forceinline__ void cpa16(uint32_t dst, const void* src) {
    asm volatile("cp.async.cg.shared.global [%0], [%1], 16;" :: "r"(dst), "l"(src));
}
#define CP_COMMIT() asm volatile("cp.async.commit_group;" ::: "memory")
#define CP_WAIT(n)  asm volatile("cp.async.wait_group %0;" :: "n"(n) : "memory")

__device__ __forceinline__ void ldsm4(uint32_t* r, uint32_t addr) {
    asm volatile("ldmatrix.sync.aligned.m8n8.x4.shared.b16 {%0,%1,%2,%3}, [%4];"
                 : "=r"(r[0]), "=r"(r[1]), "=r"(r[2]), "=r"(r[3]) : "r"(addr));
}
__device__ __forceinline__ void ldsm2(uint32_t* r, uint32_t addr) {
    asm volatile("ldmatrix.sync.aligned.m8n8.x2.shared.b16 {%0,%1}, [%2];"
                 : "=r"(r[0]), "=r"(r[1]) : "r"(addr));
}
__device__ __forceinline__ void mma_s8(int* c, const uint32_t* a, const uint32_t* b) {
    asm volatile("mma.sync.aligned.m16n8k32.row.col.s32.s8.s8.s32 "
                 "{%0,%1,%2,%3}, {%4,%5,%6,%7}, {%8,%9}, {%0,%1,%2,%3};"
                 : "+r"(c[0]), "+r"(c[1]), "+r"(c[2]), "+r"(c[3])
                 : "r"(a[0]), "r"(a[1]), "r"(a[2]), "r"(a[3]), "r"(b[0]), "r"(b[1]));
}
__device__ __forceinline__ void red2(float* p, float x, float y) {
    asm volatile("red.global.add.v2.f32 [%0], {%1,%2};" :: "l"(p), "f"(x), "f"(y) : "memory");
}

// quantize 4 floats -> packed s8 hi + s8 lo (x = s*(hi + lo/128) + O(s/256))
__device__ __forceinline__ void quant4(const float* x, float inv, uint32_t& hi, uint32_t& lo) {
    uint32_t h = 0, l = 0;
    #pragma unroll
    for (int i = 0; i < 4; ++i) {
        float t = x[i] * inv;
        float hf = rintf(t);
        int hv = (int)hf;
        int lv = (int)rintf((t - hf) * 128.f);
        h |= ((uint32_t)hv & 255u) << (i * 8);
        l |= ((uint32_t)lv & 255u) << (i * 8);
    }
    hi = h; lo = l;
}
__device__ __forceinline__ uint32_t quant2(float a, float b, float inv, uint32_t& lo) {
    float ta = a * inv, tb = b * inv;
    float ha = rintf(ta), hb = rintf(tb);
    int la = (int)rintf((ta - ha) * 128.f), lb = (int)rintf((tb - hb) * 128.f);
    lo = ((uint32_t)la & 255u) | (((uint32_t)lb & 255u) << 8);
    return ((uint32_t)(int)ha & 255u) | (((uint32_t)(int)hb & 255u) << 8);
}

// ---------------- smem layout (byte offsets) -------------------------------
#define X_HI 0            // [64 rows][272B] s8 (cols: from 0-127, to 128-255)
#define X_LO 17408
#define H_HI 34816        // [64][272B]
#define H_LO 52224
#define WSTG 69632        // [2 stages][hi/lo][256n x 48B]
#define STG_BYTES 12288
#define SBIAS  118784     // 256 f
#define SWEF   119808     // 256 f
#define SBSC   120832     // 256 f
#define SEF    121856     // 64 f
#define SRMAX  122112     // 16 f
#define EDGE_SMEM 122368

// ---------------- prep: per-col scale + int8 hi/lo split, [n][k] layout ----
// swap!=0 swaps k-halves (k^128) so one X=[from|to] buffer serves both dirs.
__global__ void prep_w_i8(const float* __restrict__ W, int swap,
                          int8_t* __restrict__ oh, int8_t* __restrict__ ol,
                          float* __restrict__ osc)
{
    __shared__ float red[256];
    int n = blockIdx.x, k = threadIdx.x;
    int ks = swap ? (k ^ 128) : k;
    float v = W[ks * 256 + n];
    red[k] = fabsf(v);
    __syncthreads();
    for (int s = 128; s > 0; s >>= 1) {
        if (k < s) red[k] = fmaxf(red[k], red[k + s]);
        __syncthreads();
    }
    float amax = fmaxf(red[0], 1e-30f);
    if (k == 0) osc[n] = amax / 127.f;
    float t = v * (127.f / amax);
    float hf = rintf(t);
    oh[n * 256 + k] = (int8_t)(int)hf;
    ol[n * 256 + k] = (int8_t)(int)rintf((t - hf) * 128.f);
}

__global__ void zero_agg_kernel(int n4) {
    float4* p = reinterpret_cast<float4*>(g_agg);
    int i = blockIdx.x * blockDim.x + threadIdx.x;
    int stride = gridDim.x * blockDim.x;
    float4 z = make_float4(0.f, 0.f, 0.f, 0.f);
    for (; i < n4; i += stride) p[i] = z;
}

// ---------------- K=256 int8 GEMM phase, cp.async double-buffered ----------
// 16 warps: 4m x 4n; warp tile 16x64 (8 n-frags). Per k32-chunk: A 2x ldsm4,
// per nf: 2x ldsm2 + 3 IMMA (P += ah*bh; Q += ah*bl + al*bh).
__device__ __forceinline__ void gemm_i8(
    const int8_t* __restrict__ gh, const int8_t* __restrict__ gl,
    uint32_t smb, int tid, uint32_t aHI, uint32_t aLO, uint32_t bOff,
    int P[8][4], int Q[8][4])
{
    auto copy_chunk = [&](int s, int c) {
        #pragma unroll
        for (int i = 0; i < 2; ++i) {
            int idx = i * 512 + tid;
            int h = idx >> 9, r = idx & 511;
            int n = r >> 1, seg = r & 1;
            const int8_t* src = (h ? gl : gh) + n * 256 + c * 32 + seg * 16;
            uint32_t dst = smb + WSTG +
                (uint32_t)(s * 2 * STG_BYTES + h * STG_BYTES + n * 48 + seg * 16);
            cpa16(dst, src);
        }
    };

    copy_chunk(0, 0);
    CP_COMMIT();
    for (int c = 0; c < 8; ++c) {
        const int s = c & 1;
        if (c < 7) { copy_chunk(s ^ 1, c + 1); CP_COMMIT(); CP_WAIT(1); }
        else       { CP_WAIT(0); }
        __syncthreads();
        uint32_t Ah[4], Al[4];
        ldsm4(Ah, aHI + c * 32);
        ldsm4(Al, aLO + c * 32);
        const uint32_t wb = smb + WSTG + (uint32_t)(s * 2 * STG_BYTES) + bOff;
        #pragma unroll
        for (int nf = 0; nf < 8; ++nf) {
            uint32_t Bh[2], Bl[2];
            ldsm2(Bh, wb + nf * 384);
            ldsm2(Bl, wb + nf * 384 + STG_BYTES);
            mma_s8(P[nf], Ah, Bh);
            mma_s8(Q[nf], Ah, Bl);
            mma_s8(Q[nf], Al, Bh);
        }
        __syncthreads();
    }
}

// ---------------- edge kernel: both directions, int8-split IMMA ------------
__global__ __launch_bounds__(512, 1)
void edge_mma_kernel(const float* __restrict__ ns, const float* __restrict__ ef,
                     const int* __restrict__ fidx, const int* __restrict__ tidx,
                     const float* __restrict__ W1, const float* __restrict__ RW1,
                     const float* __restrict__ b1, const float* __restrict__ b2,
                     const float* __restrict__ Rb1, const float* __restrict__ Rb2,
                     int E)
{
    extern __shared__ float smf[];
    char* smc = reinterpret_cast<char*>(smf);
    const uint32_t smb = smem_u32(smf);
    const int tid = threadIdx.x, wid = tid >> 5, lane = tid & 31;
    const int wm = wid & 3, wn = wid >> 2;
    const int m0 = wm * 16, n0 = wn * 64;
    const int e0 = blockIdx.x * 64;

    float* sBias = reinterpret_cast<float*>(smc + SBIAS);
    float* sWef  = reinterpret_cast<float*>(smc + SWEF);
    float* sBsc  = reinterpret_cast<float*>(smc + SBSC);
    float* sEf   = reinterpret_cast<float*>(smc + SEF);
    float* sRMax = reinterpret_cast<float*>(smc + SRMAX);

    // ---- gather X once, tile max, quantize to s8 hi/lo ----------------------
    float fv[16], tv[16];
    {
        const int row = tid >> 3, q = tid & 7;
        int e = e0 + row; if (e >= E) e = E - 1;
        const float4* pf = reinterpret_cast<const float4*>(ns + (size_t)fidx[e] * 128 + q * 16);
        const float4* pt = reinterpret_cast<const float4*>(ns + (size_t)tidx[e] * 128 + q * 16);
        float am = 0.f;
        #pragma unroll
        for (int j = 0; j < 4; ++j) {
            float4 v = pf[j];
            fv[j*4+0]=v.x; fv[j*4+1]=v.y; fv[j*4+2]=v.z; fv[j*4+3]=v.w;
            float4 w = pt[j];
            tv[j*4+0]=w.x; tv[j*4+1]=w.y; tv[j*4+2]=w.z; tv[j*4+3]=w.w;
        }
        #pragma unroll
        for (int j = 0; j < 16; ++j)
            am = fmaxf(am, fmaxf(fabsf(fv[j]), fabsf(tv[j])));
        #pragma unroll
        for (int o = 16; o > 0; o >>= 1)
            am = fmaxf(am, __shfl_xor_sync(0xffffffffu, am, o));
        if (lane == 0) sRMax[wid] = am;
        if (tid < 64) sEf[tid] = (e0 + tid < E) ? ef[e0 + tid] : 0.f;
    }
    __syncthreads();
    float xmax = 1e-30f;
    #pragma unroll
    for (int i = 0; i < 16; ++i) xmax = fmaxf(xmax, sRMax[i]);
    const float sX = xmax / 127.f;
    const float invX = 127.f / xmax;
    {
        const int row = tid >> 3, q = tid & 7;
        uint32_t h0[4], l0[4], h1[4], l1[4];
        #pragma unroll
        for (int j = 0; j < 4; ++j) {
            quant4(&fv[j*4], invX, h0[j], l0[j]);
            quant4(&tv[j*4], invX, h1[j], l1[j]);
        }
        const uint32_t dF = (uint32_t)(row * 272 + q * 16);
        *reinterpret_cast<uint4*>(smc + X_HI + dF)       = make_uint4(h0[0],h0[1],h0[2],h0[3]);
        *reinterpret_cast<uint4*>(smc + X_LO + dF)       = make_uint4(l0[0],l0[1],l0[2],l0[3]);
        *reinterpret_cast<uint4*>(smc + X_HI + dF + 128) = make_uint4(h1[0],h1[1],h1[2],h1[3]);
        *reinterpret_cast<uint4*>(smc + X_LO + dF + 128) = make_uint4(l1[0],l1[1],l1[2],l1[3]);
    }

    // lane-resolved fragment addresses
    const int rA = (lane & 7) + ((lane >> 3) & 1) * 8;
    const uint32_t cAo8 = ((lane >> 4) & 1) * 16;
    const uint32_t aHIx = smb + X_HI + (uint32_t)((m0 + rA) * 272) + cAo8;
    const uint32_t aLOx = smb + X_LO + (uint32_t)((m0 + rA) * 272) + cAo8;
    const uint32_t aHIh = smb + H_HI + (uint32_t)((m0 + rA) * 272) + cAo8;
    const uint32_t aLOh = smb + H_LO + (uint32_t)((m0 + rA) * 272) + cAo8;
    const uint32_t bOff = (uint32_t)((n0 + (lane & 7)) * 48 + ((lane >> 3) & 1) * 16);
    const int r0 = m0 + (lane >> 2);

    for (int dir = 0; dir < 2; ++dir) {
        const int* iD = dir ? fidx : tidx;
        const float* bias1 = dir ? Rb1 : b1;
        const float* bias2 = dir ? Rb2 : b2;
        const float* wef = (dir ? RW1 : W1) + 65536;   // W1 row k=256 (ef col)
        const int8_t* g1h = g_w1q[dir][0]; const int8_t* g1l = g_w1q[dir][1];
        const int8_t* g2h = g_w2q[dir][0]; const int8_t* g2l = g_w2q[dir][1];

        __syncthreads();    // prior dir's readers of sBias/sBsc done
        if (tid < 256) {
            sBias[tid] = bias1[tid];
            sWef[tid]  = wef[tid];
            sBsc[tid]  = g_w1s[dir][tid];
        }
        __syncthreads();

        int P[8][4], Q[8][4];
        #pragma unroll
        for (int nf = 0; nf < 8; ++nf) {
            P[nf][0]=P[nf][1]=P[nf][2]=P[nf][3]=0;
            Q[nf][0]=Q[nf][1]=Q[nf][2]=Q[nf][3]=0;
        }
        gemm_i8(g1h, g1l, smb, tid, aHIx, aLOx, bOff, P, Q);

        // ---- L1 epilogue: dequant + bias + ef rank-1 + ReLU; tile max -------
        float h[8][4];
        const float efr  = sEf[r0];
        const float efr8 = sEf[r0 + 8];
        float hmax = 0.f;
        #pragma unroll
        for (int nf = 0; nf < 8; ++nf) {
            int cc = n0 + nf * 8 + (lane & 3) * 2;
            float s0 = sX * sBsc[cc], s1 = sX * sBsc[cc + 1];
            float w0 = sWef[cc], w1 = sWef[cc + 1];
            float bb0 = sBias[cc], bb1 = sBias[cc + 1];
            h[nf][0] = fmaxf(s0 * ((float)P[nf][0] + (float)Q[nf][0] * 0.0078125f) + bb0 + efr  * w0, 0.f);
            h[nf][1] = fmaxf(s1 * ((float)P[nf][1] + (float)Q[nf][1] * 0.0078125f) + bb1 + efr  * w1, 0.f);
            h[nf][2] = fmaxf(s0 * ((float)P[nf][2] + (float)Q[nf][2] * 0.0078125f) + bb0 + efr8 * w0, 0.f);
            h[nf][3] = fmaxf(s1 * ((float)P[nf][3] + (float)Q[nf][3] * 0.0078125f) + bb1 + efr8 * w1, 0.f);
            hmax = fmaxf(hmax, fmaxf(fmaxf(h[nf][0], h[nf][1]), fmaxf(h[nf][2], h[nf][3])));
        }
        #pragma unroll
        for (int o = 16; o > 0; o >>= 1)
            hmax = fmaxf(hmax, __shfl_xor_sync(0xffffffffu, hmax, o));
        if (lane == 0) sRMax[wid] = hmax;
        __syncthreads();    // all L1-epilogue smem reads done; sRMax visible
        if (tid < 256) {
            sBias[tid] = bias2[tid];
            sBsc[tid]  = g_w2s[dir][tid];
        }
        float hm = 1e-30f;
        #pragma unroll
        for (int i = 0; i < 16; ++i) hm = fmaxf(hm, sRMax[i]);
        const float sH = hm / 127.f, invH = 127.f / hm;
        #pragma unroll
        for (int nf = 0; nf < 8; ++nf) {
            int cc = n0 + nf * 8 + (lane & 3) * 2;
            uint32_t lo0, lo1;
            uint32_t hi0 = quant2(h[nf][0], h[nf][1], invH, lo0);
            uint32_t hi1 = quant2(h[nf][2], h[nf][3], invH, lo1);
            uint32_t d0 = (uint32_t)(r0 * 272 + cc);
            uint32_t d1 = (uint32_t)((r0 + 8) * 272 + cc);
            *reinterpret_cast<uint16_t*>(smc + H_HI + d0) = (uint16_t)hi0;
            *reinterpret_cast<uint16_t*>(smc + H_LO + d0) = (uint16_t)lo0;
            *reinterpret_cast<uint16_t*>(smc + H_HI + d1) = (uint16_t)hi1;
            *reinterpret_cast<uint16_t*>(smc + H_LO + d1) = (uint16_t)lo1;
        }
        __syncthreads();    // H visible before L2 ldmatrix

        // ---- L2: K=256 over H ----------------------------------------------
        #pragma unroll
        for (int nf = 0; nf < 8; ++nf) {
            P[nf][0]=P[nf][1]=P[nf][2]=P[nf][3]=0;
            Q[nf][0]=Q[nf][1]=Q[nf][2]=Q[nf][3]=0;
        }
        gemm_i8(g2h, g2l, smb, tid, aHIh, aLOh, bOff, P, Q);

        // ---- scatter: dequant + bias2, red.v2 into g_agg --------------------
        {
            const int er = e0 + r0, er8 = er + 8;
            const int d0 = (er < E) ? iD[er] : 0;
            const int d8 = (er8 < E) ? iD[er8] : 0;
            float* p0 = g_agg + (size_t)d0 * 256;
            float* p8 = g_agg + (size_t)d8 * 256;
            #pragma unroll
            for (int nf = 0; nf < 8; ++nf) {
                int cc = n0 + nf * 8 + (lane & 3) * 2;
                float s0 = sH * sBsc[cc], s1 = sH * sBsc[cc + 1];
                float v0 = s0 * ((float)P[nf][0] + (float)Q[nf][0] * 0.0078125f) + sBias[cc];
                float v1 = s1 * ((float)P[nf][1] + (float)Q[nf][1] * 0.0078125f) + sBias[cc + 1];
                float v2 = s0 * ((float)P[nf][2] + (float)Q[nf][2] * 0.0078125f) + sBias[cc];
                float v3 = s1 * ((float)P[nf][3] + (float)Q[nf][3] * 0.0078125f) + sBias[cc + 1];
                if (er < E)  red2(p0 + cc, v0, v1);
                if (er8 < E) red2(p8 + cc, v2, v3);
            }
        }
    }
}

// ---------------- node update MLP + residual (FFMA, proven) ----------------
__global__ __launch_bounds__(256, 1)
void node_kernel(const float* __restrict__ node_states,
                 const float* __restrict__ Wn1, const float* __restrict__ bn1,
                 const float* __restrict__ Wn2, const float* __restrict__ bn2,
                 float* __restrict__ out, int N)
{
    extern __shared__ float sm[];
    float* sA = sm;            // 64*256
    float* sS = sm + 16384;    // 64*128
    float* sH = sm + 24576;    // 64*256
    float* sW = sm + 40960;    // 32*256

    const int tid = threadIdx.x;
    const int n0  = blockIdx.x * 64;

    for (int t = tid; t < 64 * 64; t += 256) {
        int n = t >> 6, c = t & 63;
        float4 v = make_float4(0.f, 0.f, 0.f, 0.f);
        if (n0 + n < N)
            v = reinterpret_cast<const float4*>(g_agg)[(size_t)(n0 + n) * 64 + c];
        reinterpret_cast<float4*>(sA)[t] = v;
    }
    for (int t = tid; t < 64 * 32; t += 256) {
        int n = t >> 5, c = t & 31;
        float4 v = make_float4(0.f, 0.f, 0.f, 0.f);
        if (n0 + n < N)
            v = reinterpret_cast<const float4*>(node_states)[(size_t)(n0 + n) * 32 + c];
        reinterpret_cast<float4*>(sS)[t] = v;
    }
    __syncthreads();

    const int wg = tid >> 5, lane = tid & 31;
    const int nBase = wg * 8, j0 = lane * 8;

    float acc[8][8];
    #pragma unroll
    for (int jj = 0; jj < 8; ++jj) {
        float bv = bn1[j0 + jj];
        #pragma unroll
        for (int ii = 0; ii < 8; ++ii) acc[ii][jj] = bv;
    }
    for (int kt = 0; kt < 12; ++kt) {
        __syncthreads();
        {
            const float4* src = reinterpret_cast<const float4*>(Wn1 + kt * 32 * 256);
            float4* dw = reinterpret_cast<float4*>(sW);
            #pragma unroll
            for (int t0 = 0; t0 < 8; ++t0) dw[tid + t0 * 256] = src[tid + t0 * 256];
        }
        __syncthreads();
        const float* Xb; int strd;
        if (kt < 8) { Xb = sA + kt * 32;       strd = 256; }
        else        { Xb = sS + (kt - 8) * 32; strd = 128; }
        #pragma unroll 8
        for (int kk = 0; kk < 32; ++kk) {
            float xv[8];
            #pragma unroll
            for (int ii = 0; ii < 8; ++ii) xv[ii] = Xb[(nBase + ii) * strd + kk];
            float4 w0 = *reinterpret_cast<const float4*>(&sW[kk * 256 + j0]);
            float4 w1 = *reinterpret_cast<const float4*>(&sW[kk * 256 + j0 + 4]);
            float wv[8] = {w0.x, w0.y, w0.z, w0.w, w1.x, w1.y, w1.z, w1.w};
            #pragma unroll
            for (int ii = 0; ii < 8; ++ii)
                #pragma unroll
                for (int jj = 0; jj < 8; ++jj)
                    acc[ii][jj] = fmaf(xv[ii], wv[jj], acc[ii][jj]);
        }
    }
    #pragma unroll
    for (int ii = 0; ii < 8; ++ii) {
        float4 h0 = make_float4(fmaxf(acc[ii][0], 0.f), fmaxf(acc[ii][1], 0.f),
                                fmaxf(acc[ii][2], 0.f), fmaxf(acc[ii][3], 0.f));
        float4 h1 = make_float4(fmaxf(acc[ii][4], 0.f), fmaxf(acc[ii][5], 0.f),
                                fmaxf(acc[ii][6], 0.f), fmaxf(acc[ii][7], 0.f));
        *reinterpret_cast<float4*>(&sH[(nBase + ii) * 256 + j0])     = h0;
        *reinterpret_cast<float4*>(&sH[(nBase + ii) * 256 + j0 + 4]) = h1;
    }

    const int j4 = lane * 4;
    float acc2[8][4];
    #pragma unroll
    for (int jj = 0; jj < 4; ++jj) {
        float bv = bn2[j4 + jj];
        #pragma unroll
        for (int ii = 0; ii < 8; ++ii) acc2[ii][jj] = bv;
    }
    for (int kt = 0; kt < 8; ++kt) {
        __syncthreads();
        {
            const float4* src = reinterpret_cast<const float4*>(Wn2 + kt * 32 * 128);
            float4* dw = reinterpret_cast<float4*>(sW);
            #pragma unroll
            for (int t0 = 0; t0 < 4; ++t0) dw[tid + t0 * 256] = src[tid + t0 * 256];
        }
        __syncthreads();
        #pragma unroll 8
        for (int kk = 0; kk < 32; ++kk) {
            float xv[8];
            #pragma unroll
            for (int ii = 0; ii < 8; ++ii) xv[ii] = sH[(nBase + ii) * 256 + kt * 32 + kk];
            float4 w = *reinterpret_cast<const float4*>(&sW[kk * 128 + j4]);
            float wv[4] = {w.x, w.y, w.z, w.w};
            #pragma unroll
            for (int ii = 0; ii < 8; ++ii)
                #pragma unroll
                for (int jj = 0; jj < 4; ++jj)
                    acc2[ii][jj] = fmaf(xv[ii], wv[jj], acc2[ii][jj]);
        }
    }
    #pragma unroll
    for (int ii = 0; ii < 8; ++ii) {
        int n = n0 + nBase + ii;
        if (n < N) {
            float4 s = *reinterpret_cast<const float4*>(&sS[(nBase + ii) * 128 + j4]);
            float4 o = make_float4(s.x + acc2[ii][0], s.y + acc2[ii][1],
                                   s.z + acc2[ii][2], s.w + acc2[ii][3]);
            *reinterpret_cast<float4*>(&out[(size_t)n * 128 + j4]) = o;
        }
    }
}

// ---------------------------------------------------------------------------
extern "C" void kernel_launch(void* const* d_in, const int* in_sizes, int n_in,
                              void* d_out, int out_size)
{
    const float* node_states = (const float*)d_in[0];
    const float* edge_feat   = (const float*)d_in[1];
    const int*   from_idx    = (const int*)d_in[2];
    const int*   to_idx      = (const int*)d_in[3];
    const float* W1  = (const float*)d_in[4];
    const float* b1  = (const float*)d_in[5];
    const float* W2  = (const float*)d_in[6];
    const float* b2  = (const float*)d_in[7];
    const float* RW1 = (const float*)d_in[8];
    const float* Rb1 = (const float*)d_in[9];
    const float* RW2 = (const float*)d_in[10];
    const float* Rb2 = (const float*)d_in[11];
    const float* Wn1 = (const float*)d_in[12];
    const float* bn1 = (const float*)d_in[13];
    const float* Wn2 = (const float*)d_in[14];
    const float* bn2 = (const float*)d_in[15];
    float* out = (float*)d_out;

    const int N = in_sizes[0] / 128;
    const int E = in_sizes[2];

    int8_t *w1q, *w2q; float *w1s, *w2s;
    cudaGetSymbolAddress((void**)&w1q, g_w1q);
    cudaGetSymbolAddress((void**)&w2q, g_w2q);
    cudaGetSymbolAddress((void**)&w1s, g_w1s);
    cudaGetSymbolAddress((void**)&w2s, g_w2s);

    cudaFuncSetAttribute(edge_mma_kernel, cudaFuncAttributeMaxDynamicSharedMemorySize, EDGE_SMEM);
    cudaFuncSetAttribute(node_kernel, cudaFuncAttributeMaxDynamicSharedMemorySize, 49152 * 4);

    zero_agg_kernel<<<1024, 256>>>(N * 64);
    prep_w_i8<<<256, 256>>>(W1,  0, w1q,              w1q + 65536,     w1s);
    prep_w_i8<<<256, 256>>>(RW1, 1, w1q + 2 * 65536,  w1q + 3 * 65536, w1s + 256);
    prep_w_i8<<<256, 256>>>(W2,  0, w2q,              w2q + 65536,     w2s);
    prep_w_i8<<<256, 256>>>(RW2, 0, w2q + 2 * 65536,  w2q + 3 * 65536, w2s + 256);
    edge_mma_kernel<<<(E + 63) / 64, 512, EDGE_SMEM>>>(
        node_states, edge_feat, from_idx, to_idx, W1, RW1, b1, b2, Rb1, Rb2, E);
    node_kernel<<<(N + 63) / 64, 256, 49152 * 4>>>(node_states, Wn1, bn1, Wn2, bn2, out, N);
}

// round 7
// speedup vs baseline: 3.1700x; 3.1700x over previous
#include <cuda_runtime.h>
#include <cuda_fp16.h>
#include <cstdint>

#define MAX_N 50000

// ---------------- device scratch (no allocation allowed) -------------------
__device__ float  g_agg[(size_t)MAX_N * 256];       // [N][256] aggregation
__device__ __half g_w1[2][65536];                   // [dir][n*256+k] fp16 (rounded)
__device__ __half g_w2[2][65536];

// ---------------- small asm helpers ----------------------------------------
__device__ __forceinline__ uint32_t smem_u32(const void* p) {
    uint32_t a;
    asm("{ .reg .u64 t; cvta.to.shared.u64 t, %1; cvt.u32.u64 %0, t; }" : "=r"(a) : "l"(p));
    return a;
}
__device__ __forceinline__ void cpa16(uint32_t dst, const void* src) {
    asm volatile("cp.async.cg.shared.global [%0], [%1], 16;" :: "r"(dst), "l"(src));
}
#define CP_COMMIT() asm volatile("cp.async.commit_group;" ::: "memory")
#define CP_WAIT(n)  asm volatile("cp.async.wait_group %0;" :: "n"(n) : "memory")

__device__ __forceinline__ void ldsm4(uint32_t* r, uint32_t addr) {
    asm volatile("ldmatrix.sync.aligned.m8n8.x4.shared.b16 {%0,%1,%2,%3}, [%4];"
                 : "=r"(r[0]), "=r"(r[1]), "=r"(r[2]), "=r"(r[3]) : "r"(addr));
}
__device__ __forceinline__ void ldsm2(uint32_t* r, uint32_t addr) {
    asm volatile("ldmatrix.sync.aligned.m8n8.x2.shared.b16 {%0,%1}, [%2];"
                 : "=r"(r[0]), "=r"(r[1]) : "r"(addr));
}
__device__ __forceinline__ void mma16816(float* c, const uint32_t* a, const uint32_t* b) {
    asm volatile("mma.sync.aligned.m16n8k16.row.col.f32.f16.f16.f32 "
                 "{%0,%1,%2,%3}, {%4,%5,%6,%7}, {%8,%9}, {%0,%1,%2,%3};"
                 : "+f"(c[0]), "+f"(c[1]), "+f"(c[2]), "+f"(c[3])
                 : "r"(a[0]), "r"(a[1]), "r"(a[2]), "r"(a[3]), "r"(b[0]), "r"(b[1]));
}
__device__ __forceinline__ void red2(float* p, float x, float y) {
    asm volatile("red.global.add.v2.f32 [%0], {%1,%2};" :: "l"(p), "f"(x), "f"(y) : "memory");
}
__device__ __forceinline__ uint32_t pack_hi(float x, float y, uint32_t& lo) {
    __half hx = __float2half_rn(x), hy = __float2half_rn(y);
    __half lx = __float2half_rn(x - __half2float(hx));
    __half ly = __float2half_rn(y - __half2float(hy));
    __half2 l2 = __halves2half2(lx, ly);
    lo = *reinterpret_cast<uint32_t*>(&l2);
    __half2 h2 = __halves2half2(hx, hy);
    return *reinterpret_cast<uint32_t*>(&h2);
}

// ---------------- smem layout (byte offsets) -------------------------------
// X buffers: [64][136] halfs each (17,408B)
#define XF_HI 0
#define XF_LO 17408
#define XT_HI 34816
#define XT_LO 52224
// H buffers: [64][264] halfs (33,792B each)
#define SH_HI 69632
#define SH_LO 103424
// W stages: [2 stages] of [256][40] halfs (20,480B each)
#define SW_BASE 137216
// fp32 regions
#define SBIAS 178176
#define SWEF  179200
#define SEF   180224
#define EDGE_SMEM 180480

// ---------------- prep: transpose + fp16 round -----------------------------
__global__ void prep_w_kernel(const float* __restrict__ W, __half* __restrict__ oh) {
    int i = blockIdx.x * 256 + threadIdx.x;      // i = n*256 + k
    if (i >= 65536) return;
    int n = i >> 8, k = i & 255;
    oh[i] = __float2half_rn(W[k * 256 + n]);
}

__global__ void zero_agg_kernel(int n4) {
    float4* p = reinterpret_cast<float4*>(g_agg);
    int i = blockIdx.x * blockDim.x + threadIdx.x;
    int stride = gridDim.x * blockDim.x;
    float4 z = make_float4(0.f, 0.f, 0.f, 0.f);
    for (; i < n4; i += stride) p[i] = z;
}

// ---------------- K=256 GEMM phase: cp.async double-buffered ---------------
// 16 warps: 4 m-tiles x 4 n-tiles; warp tile 16x64 (8 n-fragments).
// A: fp16 hi/lo fragments from smem (2-term: (ah+al)*bh).
// B: fp16 weights [n][k] streamed in 32-K chunks.
__device__ __forceinline__ void gemm_phase(
    const __half* __restrict__ gh,
    uint32_t smb, int tid,
    uint32_t aH0, uint32_t aL0, uint32_t aH1, uint32_t aL1,
    uint32_t bB, float acc[8][4])
{
    auto copy_chunk = [&](int s, int c) {
        #pragma unroll
        for (int i = 0; i < 2; ++i) {
            int idx = i * 512 + tid;            // 1024 x 16B = 32KB? no: 16KB
            int n = idx >> 2, seg = idx & 3;
            const __half* src = gh + n * 256 + c * 32 + seg * 8;
            uint32_t dst = smb + SW_BASE + (uint32_t)(s * 20480 + n * 80 + seg * 16);
            cpa16(dst, src);
        }
    };

    copy_chunk(0, 0);
    CP_COMMIT();
    for (int c = 0; c < 8; ++c) {
        const int s = c & 1;
        if (c < 7) { copy_chunk(s ^ 1, c + 1); CP_COMMIT(); CP_WAIT(1); }
        else       { CP_WAIT(0); }
        __syncthreads();
        #pragma unroll
        for (int ks = 0; ks < 2; ++ks) {
            const int step = c * 2 + ks;
            uint32_t ah = ((step < 8) ? aH0 : aH1) + (step & 7) * 32;
            uint32_t al = ((step < 8) ? aL0 : aL1) + (step & 7) * 32;
            uint32_t Ah[4], Al[4];
            ldsm4(Ah, ah);
            ldsm4(Al, al);
            const uint32_t wrow = smb + SW_BASE + (uint32_t)(s * 20480) + bB + ks * 32;
            #pragma unroll
            for (int nf = 0; nf < 8; ++nf) {
                uint32_t Bh[2];
                ldsm2(Bh, wrow + nf * 640);
                mma16816(acc[nf], Ah, Bh);
                mma16816(acc[nf], Al, Bh);
            }
        }
        __syncthreads();
    }
}

// ---------------- edge kernel: both directions, 2-term HMMA ----------------
__global__ __launch_bounds__(512, 1)
void edge_mma_kernel(const float* __restrict__ ns, const float* __restrict__ ef,
                     const int* __restrict__ fidx, const int* __restrict__ tidx,
                     const float* __restrict__ W1, const float* __restrict__ RW1,
                     const float* __restrict__ b1, const float* __restrict__ b2,
                     const float* __restrict__ Rb1, const float* __restrict__ Rb2,
                     int E)
{
    extern __shared__ float smf[];
    char* smc = reinterpret_cast<char*>(smf);
    const uint32_t smb = smem_u32(smf);
    const int tid = threadIdx.x;
    const int wid = tid >> 5, lane = tid & 31;
    const int wm = wid & 3, wn = wid >> 2;        // 4 m-warps x 4 n-warps
    const int m0 = wm * 16, n0 = wn * 64;
    const int e0 = blockIdx.x * 64;

    float* sBiasF = reinterpret_cast<float*>(smc + SBIAS);
    float* sWefF  = reinterpret_cast<float*>(smc + SWEF);
    float* sEfF   = reinterpret_cast<float*>(smc + SEF);

    // ---- gather X (once, shared by both directions), split to fp16 hi/lo ---
    {
        const int row = tid >> 3, q = tid & 7;    // 64 rows x 8 col-chunks of 16
        int e = e0 + row; if (e >= E) e = E - 1;
        const float4* pf = reinterpret_cast<const float4*>(ns + (size_t)fidx[e] * 128 + q * 16);
        const float4* pt = reinterpret_cast<const float4*>(ns + (size_t)tidx[e] * 128 + q * 16);
        const uint32_t dst = (uint32_t)(row * 136 + q * 16) * 2;
        #pragma unroll
        for (int j = 0; j < 4; ++j) {
            float4 v = pf[j];
            uint32_t lo0, lo1;
            uint32_t hi0 = pack_hi(v.x, v.y, lo0);
            uint32_t hi1 = pack_hi(v.z, v.w, lo1);
            *reinterpret_cast<uint32_t*>(smc + XF_HI + dst + j * 8)     = hi0;
            *reinterpret_cast<uint32_t*>(smc + XF_HI + dst + j * 8 + 4) = hi1;
            *reinterpret_cast<uint32_t*>(smc + XF_LO + dst + j * 8)     = lo0;
            *reinterpret_cast<uint32_t*>(smc + XF_LO + dst + j * 8 + 4) = lo1;
            v = pt[j];
            hi0 = pack_hi(v.x, v.y, lo0);
            hi1 = pack_hi(v.z, v.w, lo1);
            *reinterpret_cast<uint32_t*>(smc + XT_HI + dst + j * 8)     = hi0;
            *reinterpret_cast<uint32_t*>(smc + XT_HI + dst + j * 8 + 4) = hi1;
            *reinterpret_cast<uint32_t*>(smc + XT_LO + dst + j * 8)     = lo0;
            *reinterpret_cast<uint32_t*>(smc + XT_LO + dst + j * 8 + 4) = lo1;
        }
        if (tid < 64) sEfF[tid] = (e0 + tid < E) ? ef[e0 + tid] : 0.f;
    }

    // lane-resolved fragment address components
    const int rA = (lane & 7) + ((lane >> 3) & 1) * 8;   // row within 16
    const int cAo = (lane >> 4) * 8;                     // col offset 0/8
    const uint32_t bB = (uint32_t)(((n0 + (lane & 7)) * 40 + ((lane >> 3) & 1) * 8) * 2);

    float acc[8][4];

    for (int dir = 0; dir < 2; ++dir) {
        const int* iD = dir ? fidx : tidx;
        const float* bias1 = dir ? Rb1 : b1;
        const float* bias2 = dir ? Rb2 : b2;
        const float* wef = (dir ? RW1 : W1) + 65536;   // row k=256 of W1
        const __half* g1h = g_w1[dir];
        const __half* g2h = g_w2[dir];
        const uint32_t fHI = dir ? XT_HI : XF_HI, fLO = dir ? XT_LO : XF_LO;
        const uint32_t sHI = dir ? XF_HI : XT_HI, sLO = dir ? XF_LO : XT_LO;

        __syncthreads();
        if (tid < 256) {
            sBiasF[tid] = bias1[tid];
            sWefF[tid]  = wef[tid];
        }
        __syncthreads();

        // ----------------- layer 1: K=256 MMA + fp32 ef rank-1 --------------
        #pragma unroll
        for (int nf = 0; nf < 8; ++nf) {
            int cc = n0 + nf * 8 + (lane & 3) * 2;
            acc[nf][0] = sBiasF[cc];
            acc[nf][1] = sBiasF[cc + 1];
            acc[nf][2] = acc[nf][0];
            acc[nf][3] = acc[nf][1];
        }
        {
            uint32_t off = (uint32_t)(((m0 + rA) * 136 + cAo) * 2);
            gemm_phase(g1h, smb, tid,
                       smb + fHI + off, smb + fLO + off,
                       smb + sHI + off, smb + sLO + off, bB, acc);
        }
        // epilogue: ef column (exact fp32), bias already in, ReLU, split -> sH
        {
            const float efr  = sEfF[m0 + (lane >> 2)];
            const float efr8 = sEfF[m0 + 8 + (lane >> 2)];
            const int r0 = m0 + (lane >> 2);
            #pragma unroll
            for (int nf = 0; nf < 8; ++nf) {
                int cc = n0 + nf * 8 + (lane & 3) * 2;
                float w0 = sWefF[cc], w1 = sWefF[cc + 1];
                float x0 = fmaxf(acc[nf][0] + efr * w0, 0.f);
                float x1 = fmaxf(acc[nf][1] + efr * w1, 0.f);
                float x2 = fmaxf(acc[nf][2] + efr8 * w0, 0.f);
                float x3 = fmaxf(acc[nf][3] + efr8 * w1, 0.f);
                uint32_t lo0, lo1;
                uint32_t hi0 = pack_hi(x0, x1, lo0);
                uint32_t hi1 = pack_hi(x2, x3, lo1);
                uint32_t d0 = (uint32_t)((r0 * 264 + cc) * 2);
                uint32_t d1 = (uint32_t)(((r0 + 8) * 264 + cc) * 2);
                *reinterpret_cast<uint32_t*>(smc + SH_HI + d0) = hi0;
                *reinterpret_cast<uint32_t*>(smc + SH_LO + d0) = lo0;
                *reinterpret_cast<uint32_t*>(smc + SH_HI + d1) = hi1;
                *reinterpret_cast<uint32_t*>(smc + SH_LO + d1) = lo1;
            }
        }
        __syncthreads();
        if (tid < 256) sBiasF[tid] = bias2[tid];
        __syncthreads();

        // ----------------- layer 2: K=256 over H -----------------------------
        #pragma unroll
        for (int nf = 0; nf < 8; ++nf) {
            int cc = n0 + nf * 8 + (lane & 3) * 2;
            acc[nf][0] = sBiasF[cc];
            acc[nf][1] = sBiasF[cc + 1];
            acc[nf][2] = acc[nf][0];
            acc[nf][3] = acc[nf][1];
        }
        {
            uint32_t off = (uint32_t)(((m0 + rA) * 264 + cAo) * 2);
            uint32_t h0 = smb + SH_HI + off, l0 = smb + SH_LO + off;
            gemm_phase(g2h, smb, tid, h0, l0, h0 + 256, l0 + 256, bB, acc);
        }

        // ----------------- scatter: red.v2 into g_agg ------------------------
        {
            const int er = e0 + m0 + (lane >> 2);
            const int er8 = er + 8;
            const int d0 = (er < E) ? iD[er] : 0;
            const int d8 = (er8 < E) ? iD[er8] : 0;
            float* p0 = g_agg + (size_t)d0 * 256;
            float* p8 = g_agg + (size_t)d8 * 256;
            #pragma unroll
            for (int nf = 0; nf < 8; ++nf) {
                int cc = n0 + nf * 8 + (lane & 3) * 2;
                if (er < E)  red2(p0 + cc, acc[nf][0], acc[nf][1]);
                if (er8 < E) red2(p8 + cc, acc[nf][2], acc[nf][3]);
            }
        }
    }
}

// ---------------- node update MLP + residual (FFMA, proven) ----------------
__global__ __launch_bounds__(256, 1)
void node_kernel(const float* __restrict__ node_states,
                 const float* __restrict__ Wn1, const float* __restrict__ bn1,
                 const float* __restrict__ Wn2, const float* __restrict__ bn2,
                 float* __restrict__ out, int N)
{
    extern __shared__ float sm[];
    float* sA = sm;            // 64*256
    float* sS = sm + 16384;    // 64*128
    float* sH = sm + 24576;    // 64*256
    float* sW = sm + 40960;    // 32*256

    const int tid = threadIdx.x;
    const int n0  = blockIdx.x * 64;

    for (int t = tid; t < 64 * 64; t += 256) {
        int n = t >> 6, c = t & 63;
        float4 v = make_float4(0.f, 0.f, 0.f, 0.f);
        if (n0 + n < N)
            v = reinterpret_cast<const float4*>(g_agg)[(size_t)(n0 + n) * 64 + c];
        reinterpret_cast<float4*>(sA)[t] = v;
    }
    for (int t = tid; t < 64 * 32; t += 256) {
        int n = t >> 5, c = t & 31;
        float4 v = make_float4(0.f, 0.f, 0.f, 0.f);
        if (n0 + n < N)
            v = reinterpret_cast<const float4*>(node_states)[(size_t)(n0 + n) * 32 + c];
        reinterpret_cast<float4*>(sS)[t] = v;
    }
    __syncthreads();

    const int wg = tid >> 5, lane = tid & 31;
    const int nBase = wg * 8, j0 = lane * 8;

    float acc[8][8];
    #pragma unroll
    for (int jj = 0; jj < 8; ++jj) {
        float bv = bn1[j0 + jj];
        #pragma unroll
        for (int ii = 0; ii < 8; ++ii) acc[ii][jj] = bv;
    }
    for (int kt = 0; kt < 12; ++kt) {
        __syncthreads();
        {
            const float4* src = reinterpret_cast<const float4*>(Wn1 + kt * 32 * 256);
            float4* dw = reinterpret_cast<float4*>(sW);
            #pragma unroll
            for (int t0 = 0; t0 < 8; ++t0) dw[tid + t0 * 256] = src[tid + t0 * 256];
        }
        __syncthreads();
        const float* Xb; int strd;
        if (kt < 8) { Xb = sA + kt * 32;       strd = 256; }
        else        { Xb = sS + (kt - 8) * 32; strd = 128; }
        #pragma unroll 8
        for (int kk = 0; kk < 32; ++kk) {
            float xv[8];
            #pragma unroll
            for (int ii = 0; ii < 8; ++ii) xv[ii] = Xb[(nBase + ii) * strd + kk];
            float4 w0 = *reinterpret_cast<const float4*>(&sW[kk * 256 + j0]);
            float4 w1 = *reinterpret_cast<const float4*>(&sW[kk * 256 + j0 + 4]);
            float wv[8] = {w0.x, w0.y, w0.z, w0.w, w1.x, w1.y, w1.z, w1.w};
            #pragma unroll
            for (int ii = 0; ii < 8; ++ii)
                #pragma unroll
                for (int jj = 0; jj < 8; ++jj)
                    acc[ii][jj] = fmaf(xv[ii], wv[jj], acc[ii][jj]);
        }
    }
    #pragma unroll
    for (int ii = 0; ii < 8; ++ii) {
        float4 h0 = make_float4(fmaxf(acc[ii][0], 0.f), fmaxf(acc[ii][1], 0.f),
                                fmaxf(acc[ii][2], 0.f), fmaxf(acc[ii][3], 0.f));
        float4 h1 = make_float4(fmaxf(acc[ii][4], 0.f), fmaxf(acc[ii][5], 0.f),
                                fmaxf(acc[ii][6], 0.f), fmaxf(acc[ii][7], 0.f));
        *reinterpret_cast<float4*>(&sH[(nBase + ii) * 256 + j0])     = h0;
        *reinterpret_cast<float4*>(&sH[(nBase + ii) * 256 + j0 + 4]) = h1;
    }

    const int j4 = lane * 4;
    float acc2[8][4];
    #pragma unroll
    for (int jj = 0; jj < 4; ++jj) {
        float bv = bn2[j4 + jj];
        #pragma unroll
        for (int ii = 0; ii < 8; ++ii) acc2[ii][jj] = bv;
    }
    for (int kt = 0; kt < 8; ++kt) {
        __syncthreads();
        {
            const float4* src = reinterpret_cast<const float4*>(Wn2 + kt * 32 * 128);
            float4* dw = reinterpret_cast<float4*>(sW);
            #pragma unroll
            for (int t0 = 0; t0 < 4; ++t0) dw[tid + t0 * 256] = src[tid + t0 * 256];
        }
        __syncthreads();
        #pragma unroll 8
        for (int kk = 0; kk < 32; ++kk) {
            float xv[8];
            #pragma unroll
            for (int ii = 0; ii < 8; ++ii) xv[ii] = sH[(nBase + ii) * 256 + kt * 32 + kk];
            float4 w = *reinterpret_cast<const float4*>(&sW[kk * 128 + j4]);
            float wv[4] = {w.x, w.y, w.z, w.w};
            #pragma unroll
            for (int ii = 0; ii < 8; ++ii)
                #pragma unroll
                for (int jj = 0; jj < 4; ++jj)
                    acc2[ii][jj] = fmaf(xv[ii], wv[jj], acc2[ii][jj]);
        }
    }
    #pragma unroll
    for (int ii = 0; ii < 8; ++ii) {
        int n = n0 + nBase + ii;
        if (n < N) {
            float4 s = *reinterpret_cast<const float4*>(&sS[(nBase + ii) * 128 + j4]);
            float4 o = make_float4(s.x + acc2[ii][0], s.y + acc2[ii][1],
                                   s.z + acc2[ii][2], s.w + acc2[ii][3]);
            *reinterpret_cast<float4*>(&out[(size_t)n * 128 + j4]) = o;
        }
    }
}

// ---------------------------------------------------------------------------
extern "C" void kernel_launch(void* const* d_in, const int* in_sizes, int n_in,
                              void* d_out, int out_size)
{
    const float* node_states = (const float*)d_in[0];
    const float* edge_feat   = (const float*)d_in[1];
    const int*   from_idx    = (const int*)d_in[2];
    const int*   to_idx      = (const int*)d_in[3];
    const float* W1  = (const float*)d_in[4];
    const float* b1  = (const float*)d_in[5];
    const float* W2  = (const float*)d_in[6];
    const float* b2  = (const float*)d_in[7];
    const float* RW1 = (const float*)d_in[8];
    const float* Rb1 = (const float*)d_in[9];
    const float* RW2 = (const float*)d_in[10];
    const float* Rb2 = (const float*)d_in[11];
    const float* Wn1 = (const float*)d_in[12];
    const float* bn1 = (const float*)d_in[13];
    const float* Wn2 = (const float*)d_in[14];
    const float* bn2 = (const float*)d_in[15];
    float* out = (float*)d_out;

    const int N = in_sizes[0] / 128;
    const int E = in_sizes[2];

    __half* w1p; __half* w2p;
    cudaGetSymbolAddress((void**)&w1p, g_w1);
    cudaGetSymbolAddress((void**)&w2p, g_w2);

    cudaFuncSetAttribute(edge_mma_kernel, cudaFuncAttributeMaxDynamicSharedMemorySize, EDGE_SMEM);
    cudaFuncSetAttribute(node_kernel, cudaFuncAttributeMaxDynamicSharedMemorySize, 49152 * 4);

    zero_agg_kernel<<<1024, 256>>>(N * 64);
    prep_w_kernel<<<256, 256>>>(W1,  w1p);
    prep_w_kernel<<<256, 256>>>(RW1, w1p + 65536);
    prep_w_kernel<<<256, 256>>>(W2,  w2p);
    prep_w_kernel<<<256, 256>>>(RW2, w2p + 65536);
    edge_mma_kernel<<<(E + 63) / 64, 512, EDGE_SMEM>>>(
        node_states, edge_feat, from_idx, to_idx, W1, RW1, b1, b2, Rb1, Rb2, E);
    node_kernel<<<(N + 63) / 64, 256, 49152 * 4>>>(node_states, Wn1, bn1, Wn2, bn2, out, N);
}

// round 8
// speedup vs baseline: 3.1713x; 1.0004x over previous
#include <cuda_runtime.h>
#include <cuda_fp16.h>
#include <cstdint>

#define MAX_N 50000

// ---------------- device scratch (no allocation allowed) -------------------
__device__ float  g_Y[(size_t)MAX_N * 1024];   // [N][4][256] node-level L1 products
__device__ float  g_agg[(size_t)MAX_N * 256];  // [N][256] aggregation
__device__ __half g_w2[2][65536];              // [dir][n*256+k] fp16 W2

// ---------------- small asm helpers ----------------------------------------
__device__ __forceinline__ uint32_t smem_u32(const void* p) {
    uint32_t a;
    asm("{ .reg .u64 t; cvta.to.shared.u64 t, %1; cvt.u32.u64 %0, t; }" : "=r"(a) : "l"(p));
    return a;
}
__device__ __forceinline__ void cpa16(uint32_t dst, const void* src) {
    asm volatile("cp.async.cg.shared.global [%0], [%1], 16;" :: "r"(dst), "l"(src));
}
#define CP_COMMIT() asm volatile("cp.async.commit_group;" ::: "memory")
#define CP_WAIT(n)  asm volatile("cp.async.wait_group %0;" :: "n"(n) : "memory")

__device__ __forceinline__ void ldsm4(uint32_t* r, uint32_t addr) {
    asm volatile("ldmatrix.sync.aligned.m8n8.x4.shared.b16 {%0,%1,%2,%3}, [%4];"
                 : "=r"(r[0]), "=r"(r[1]), "=r"(r[2]), "=r"(r[3]) : "r"(addr));
}
__device__ __forceinline__ void ldsm2(uint32_t* r, uint32_t addr) {
    asm volatile("ldmatrix.sync.aligned.m8n8.x2.shared.b16 {%0,%1}, [%2];"
                 : "=r"(r[0]), "=r"(r[1]) : "r"(addr));
}
__device__ __forceinline__ void mma16816(float* c, const uint32_t* a, const uint32_t* b) {
    asm volatile("mma.sync.aligned.m16n8k16.row.col.f32.f16.f16.f32 "
                 "{%0,%1,%2,%3}, {%4,%5,%6,%7}, {%8,%9}, {%0,%1,%2,%3};"
                 : "+f"(c[0]), "+f"(c[1]), "+f"(c[2]), "+f"(c[3])
                 : "r"(a[0]), "r"(a[1]), "r"(a[2]), "r"(a[3]), "r"(b[0]), "r"(b[1]));
}
__device__ __forceinline__ void red2(float* p, float x, float y) {
    asm volatile("red.global.add.v2.f32 [%0], {%1,%2};" :: "l"(p), "f"(x), "f"(y) : "memory");
}

// ---------------- edge-kernel smem layout (byte offsets) --------------------
#define SH    0            // [64 rows][264 halfs] hidden (stride 528B) = 33,792B
#define SWB   33792        // 2 stages x [256 n][40 halfs] = 2 x 20,480B
#define SBIAS 74752        // 256 f32
#define SWEF  75776        // 256 f32
#define SEF   76800        // 64 f32
#define ESMEM 77056

// ---------------- prep: W2 transpose + fp16 round ---------------------------
__global__ void prep_w_kernel(const float* __restrict__ W, __half* __restrict__ oh) {
    int i = blockIdx.x * 256 + threadIdx.x;      // i = n*256 + k
    if (i >= 65536) return;
    int n = i >> 8, k = i & 255;
    oh[i] = __float2half_rn(W[k * 256 + n]);
}

__global__ void zero_agg_kernel(int n4) {
    float4* p = reinterpret_cast<float4*>(g_agg);
    int i = blockIdx.x * blockDim.x + threadIdx.x;
    int stride = gridDim.x * blockDim.x;
    float4 z = make_float4(0.f, 0.f, 0.f, 0.f);
    for (; i < n4; i += stride) p[i] = z;
}

// ---------------- node-level L1 precompute (exact fp32 FFMA) ----------------
// Y[n][0][:] = ns[n] @ W1[0:128]            (forward, from-side)
// Y[n][1][:] = ns[n] @ W1[128:256]  + b1    (forward, to-side)
// Y[n][2][:] = ns[n] @ RW1[0:128]           (reverse, to-side)
// Y[n][3][:] = ns[n] @ RW1[128:256] + Rb1   (reverse, from-side)
__global__ __launch_bounds__(256, 1)
void precompute_y(const float* __restrict__ ns,
                  const float* __restrict__ W1, const float* __restrict__ RW1,
                  const float* __restrict__ b1, const float* __restrict__ Rb1, int N)
{
    extern __shared__ float sm[];
    float* sS = sm;           // 64*128
    float* sW = sm + 8192;    // 32*256
    const int tid = threadIdx.x;
    const int n0 = blockIdx.x * 64;

    for (int t = tid; t < 64 * 32; t += 256) {
        int n = t >> 5, c = t & 31;
        float4 v = make_float4(0.f, 0.f, 0.f, 0.f);
        if (n0 + n < N)
            v = reinterpret_cast<const float4*>(ns)[(size_t)(n0 + n) * 32 + c];
        reinterpret_cast<float4*>(sS)[t] = v;
    }

    const int wg = tid >> 5, lane = tid & 31;
    const int nb = wg * 8, j0 = lane * 8;

    for (int q = 0; q < 4; ++q) {
        const float* Wsrc = (q < 2) ? W1 : RW1;
        const int rowoff = (q & 1) * 128;
        float acc[8][8];
        #pragma unroll
        for (int jj = 0; jj < 8; ++jj) {
            float bv = (q == 1) ? b1[j0 + jj] : ((q == 3) ? Rb1[j0 + jj] : 0.f);
            #pragma unroll
            for (int ii = 0; ii < 8; ++ii) acc[ii][jj] = bv;
        }
        for (int kt = 0; kt < 4; ++kt) {
            __syncthreads();
            {
                const float4* src = reinterpret_cast<const float4*>(Wsrc + (rowoff + kt * 32) * 256);
                float4* dw = reinterpret_cast<float4*>(sW);
                #pragma unroll
                for (int t0 = 0; t0 < 8; ++t0) dw[tid + t0 * 256] = src[tid + t0 * 256];
            }
            __syncthreads();
            #pragma unroll 8
            for (int kk = 0; kk < 32; ++kk) {
                float xv[8];
                #pragma unroll
                for (int ii = 0; ii < 8; ++ii) xv[ii] = sS[(nb + ii) * 128 + kt * 32 + kk];
                float4 w0 = *reinterpret_cast<const float4*>(&sW[kk * 256 + j0]);
                float4 w1 = *reinterpret_cast<const float4*>(&sW[kk * 256 + j0 + 4]);
                float wv[8] = {w0.x, w0.y, w0.z, w0.w, w1.x, w1.y, w1.z, w1.w};
                #pragma unroll
                for (int ii = 0; ii < 8; ++ii)
                    #pragma unroll
                    for (int jj = 0; jj < 8; ++jj)
                        acc[ii][jj] = fmaf(xv[ii], wv[jj], acc[ii][jj]);
            }
        }
        #pragma unroll
        for (int ii = 0; ii < 8; ++ii) {
            int n = n0 + nb + ii;
            if (n < N) {
                float* dst = g_Y + (size_t)n * 1024 + q * 256 + j0;
                *reinterpret_cast<float4*>(dst)     = make_float4(acc[ii][0], acc[ii][1], acc[ii][2], acc[ii][3]);
                *reinterpret_cast<float4*>(dst + 4) = make_float4(acc[ii][4], acc[ii][5], acc[ii][6], acc[ii][7]);
            }
        }
    }
}

// ---------------- L2 GEMM: single-term fp16, cp.async double-buffered -------
__device__ __forceinline__ void gemm_l2(const __half* __restrict__ gw,
                                        uint32_t smb, int tid,
                                        uint32_t aH0, uint32_t aH1, uint32_t bB,
                                        float acc[8][4])
{
    auto copy_chunk = [&](int s, int c) {
        #pragma unroll
        for (int i = 0; i < 2; ++i) {
            int idx = i * 512 + tid;
            int n = idx >> 2, seg = idx & 3;
            const __half* src = gw + n * 256 + c * 32 + seg * 8;
            uint32_t dst = smb + SWB + (uint32_t)(s * 20480 + n * 80 + seg * 16);
            cpa16(dst, src);
        }
    };

    copy_chunk(0, 0);
    CP_COMMIT();
    for (int c = 0; c < 8; ++c) {
        const int s = c & 1;
        if (c < 7) { copy_chunk(s ^ 1, c + 1); CP_COMMIT(); CP_WAIT(1); }
        else       { CP_WAIT(0); }
        __syncthreads();
        #pragma unroll
        for (int ks = 0; ks < 2; ++ks) {
            const int step = c * 2 + ks;
            uint32_t ah = ((step < 8) ? aH0 : aH1) + (step & 7) * 32;
            uint32_t Ah[4];
            ldsm4(Ah, ah);
            const uint32_t wrow = smb + SWB + (uint32_t)(s * 20480) + bB + ks * 32;
            #pragma unroll
            for (int nf = 0; nf < 8; ++nf) {
                uint32_t Bh[2];
                ldsm2(Bh, wrow + nf * 640);
                mma16816(acc[nf], Ah, Bh);
            }
        }
        __syncthreads();
    }
}

// ---------------- edge kernel: gather-combine L1 + single-term L2 ----------
__global__ __launch_bounds__(512, 2)
void edge_mma_kernel(const float* __restrict__ ef,
                     const int* __restrict__ fidx, const int* __restrict__ tidx,
                     const float* __restrict__ W1, const float* __restrict__ RW1,
                     const float* __restrict__ b2, const float* __restrict__ Rb2,
                     int E)
{
    extern __shared__ float smf[];
    char* smc = reinterpret_cast<char*>(smf);
    const uint32_t smb = smem_u32(smf);
    const int tid = threadIdx.x;
    const int wid = tid >> 5, lane = tid & 31;
    const int wm = wid & 3, wn = wid >> 2;       // 4 m-warps x 4 n-warps
    const int m0 = wm * 16, n0 = wn * 64;
    const int e0 = blockIdx.x * 64;

    float* sBias = reinterpret_cast<float*>(smc + SBIAS);
    float* sWef  = reinterpret_cast<float*>(smc + SWEF);
    float* sEf   = reinterpret_cast<float*>(smc + SEF);

    if (tid < 64) sEf[tid] = (e0 + tid < E) ? ef[e0 + tid] : 0.f;

    // lane-resolved fragment addresses (A from sH, stride 264 halfs)
    const int rA = (lane & 7) + ((lane >> 3) & 1) * 8;
    const int cAo = (lane >> 4) * 8;
    const uint32_t aH0 = smb + SH + (uint32_t)(((m0 + rA) * 264 + cAo) * 2);
    const uint32_t aH1 = aH0 + 256;              // +128 cols
    const uint32_t bB = (uint32_t)(((n0 + (lane & 7)) * 40 + ((lane >> 3) & 1) * 8) * 2);
    const int r0 = m0 + (lane >> 2);

    for (int dir = 0; dir < 2; ++dir) {
        const int* iD = dir ? fidx : tidx;       // scatter destination
        const float* bias2 = dir ? Rb2 : b2;
        const float* wef = (dir ? RW1 : W1) + 65536;    // W1 row k=256 (ef col)
        const __half* gw = g_w2[dir];

        __syncthreads();                          // prior dir's smem readers done
        if (tid < 256) {
            sBias[tid] = bias2[tid];
            sWef[tid]  = wef[tid];
        }
        __syncthreads();

        // ---- L1 combine: h = relu(Ya[src1] + Yb[src2] + ef*wef) -> fp16 sH --
        {
            const int row = tid >> 3, q = tid & 7;
            int e = e0 + row; if (e >= E) e = E - 1;
            const int f = fidx[e], t = tidx[e];
            // forward: Y0[f] + Y1[t];  reverse: Y2[t] + Y3[f]  (biases folded)
            const float4* A4 = reinterpret_cast<const float4*>(
                g_Y + (size_t)(dir ? t : f) * 1024 + (dir ? 512 : 0)) + q * 8;
            const float4* B4 = reinterpret_cast<const float4*>(
                g_Y + (size_t)(dir ? f : t) * 1024 + (dir ? 768 : 256)) + q * 8;
            const float efv = sEf[row];
            #pragma unroll
            for (int i = 0; i < 8; ++i) {
                float4 a = A4[i], b = B4[i];
                float4 w = *reinterpret_cast<const float4*>(&sWef[q * 32 + i * 4]);
                float h0 = fmaxf(a.x + b.x + efv * w.x, 0.f);
                float h1 = fmaxf(a.y + b.y + efv * w.y, 0.f);
                float h2 = fmaxf(a.z + b.z + efv * w.z, 0.f);
                float h3 = fmaxf(a.w + b.w + efv * w.w, 0.f);
                __half2 p0 = __floats2half2_rn(h0, h1);
                __half2 p1 = __floats2half2_rn(h2, h3);
                uint2 pk;
                pk.x = *reinterpret_cast<uint32_t*>(&p0);
                pk.y = *reinterpret_cast<uint32_t*>(&p1);
                *reinterpret_cast<uint2*>(smc + SH + row * 528 + (q * 32 + i * 4) * 2) = pk;
            }
        }
        __syncthreads();                          // sH visible to ldmatrix

        // ---- L2: msg = h @ W2 + b2 (single-term fp16 HMMA) ------------------
        float acc[8][4];
        #pragma unroll
        for (int nf = 0; nf < 8; ++nf) {
            int cc = n0 + nf * 8 + (lane & 3) * 2;
            acc[nf][0] = sBias[cc];
            acc[nf][1] = sBias[cc + 1];
            acc[nf][2] = acc[nf][0];
            acc[nf][3] = acc[nf][1];
        }
        gemm_l2(gw, smb, tid, aH0, aH1, bB, acc);

        // ---- scatter: red.v2 into g_agg -------------------------------------
        {
            const int er = e0 + r0, er8 = er + 8;
            const int d0 = (er < E) ? iD[er] : 0;
            const int d8 = (er8 < E) ? iD[er8] : 0;
            float* p0 = g_agg + (size_t)d0 * 256;
            float* p8 = g_agg + (size_t)d8 * 256;
            #pragma unroll
            for (int nf = 0; nf < 8; ++nf) {
                int cc = n0 + nf * 8 + (lane & 3) * 2;
                if (er < E)  red2(p0 + cc, acc[nf][0], acc[nf][1]);
                if (er8 < E) red2(p8 + cc, acc[nf][2], acc[nf][3]);
            }
        }
    }
}

// ---------------- node update MLP + residual (FFMA, proven) ----------------
__global__ __launch_bounds__(256, 1)
void node_kernel(const float* __restrict__ node_states,
                 const float* __restrict__ Wn1, const float* __restrict__ bn1,
                 const float* __restrict__ Wn2, const float* __restrict__ bn2,
                 float* __restrict__ out, int N)
{
    extern __shared__ float sm[];
    float* sA = sm;            // 64*256
    float* sS = sm + 16384;    // 64*128
    float* sH = sm + 24576;    // 64*256
    float* sW = sm + 40960;    // 32*256

    const int tid = threadIdx.x;
    const int n0  = blockIdx.x * 64;

    for (int t = tid; t < 64 * 64; t += 256) {
        int n = t >> 6, c = t & 63;
        float4 v = make_float4(0.f, 0.f, 0.f, 0.f);
        if (n0 + n < N)
            v = reinterpret_cast<const float4*>(g_agg)[(size_t)(n0 + n) * 64 + c];
        reinterpret_cast<float4*>(sA)[t] = v;
    }
    for (int t = tid; t < 64 * 32; t += 256) {
        int n = t >> 5, c = t & 31;
        float4 v = make_float4(0.f, 0.f, 0.f, 0.f);
        if (n0 + n < N)
            v = reinterpret_cast<const float4*>(node_states)[(size_t)(n0 + n) * 32 + c];
        reinterpret_cast<float4*>(sS)[t] = v;
    }
    __syncthreads();

    const int wg = tid >> 5, lane = tid & 31;
    const int nBase = wg * 8, j0 = lane * 8;

    float acc[8][8];
    #pragma unroll
    for (int jj = 0; jj < 8; ++jj) {
        float bv = bn1[j0 + jj];
        #pragma unroll
        for (int ii = 0; ii < 8; ++ii) acc[ii][jj] = bv;
    }
    for (int kt = 0; kt < 12; ++kt) {
        __syncthreads();
        {
            const float4* src = reinterpret_cast<const float4*>(Wn1 + kt * 32 * 256);
            float4* dw = reinterpret_cast<float4*>(sW);
            #pragma unroll
            for (int t0 = 0; t0 < 8; ++t0) dw[tid + t0 * 256] = src[tid + t0 * 256];
        }
        __syncthreads();
        const float* Xb; int strd;
        if (kt < 8) { Xb = sA + kt * 32;       strd = 256; }
        else        { Xb = sS + (kt - 8) * 32; strd = 128; }
        #pragma unroll 8
        for (int kk = 0; kk < 32; ++kk) {
            float xv[8];
            #pragma unroll
            for (int ii = 0; ii < 8; ++ii) xv[ii] = Xb[(nBase + ii) * strd + kk];
            float4 w0 = *reinterpret_cast<const float4*>(&sW[kk * 256 + j0]);
            float4 w1 = *reinterpret_cast<const float4*>(&sW[kk * 256 + j0 + 4]);
            float wv[8] = {w0.x, w0.y, w0.z, w0.w, w1.x, w1.y, w1.z, w1.w};
            #pragma unroll
            for (int ii = 0; ii < 8; ++ii)
                #pragma unroll
                for (int jj = 0; jj < 8; ++jj)
                    acc[ii][jj] = fmaf(xv[ii], wv[jj], acc[ii][jj]);
        }
    }
    #pragma unroll
    for (int ii = 0; ii < 8; ++ii) {
        float4 h0 = make_float4(fmaxf(acc[ii][0], 0.f), fmaxf(acc[ii][1], 0.f),
                                fmaxf(acc[ii][2], 0.f), fmaxf(acc[ii][3], 0.f));
        float4 h1 = make_float4(fmaxf(acc[ii][4], 0.f), fmaxf(acc[ii][5], 0.f),
                                fmaxf(acc[ii][6], 0.f), fmaxf(acc[ii][7], 0.f));
        *reinterpret_cast<float4*>(&sH[(nBase + ii) * 256 + j0])     = h0;
        *reinterpret_cast<float4*>(&sH[(nBase + ii) * 256 + j0 + 4]) = h1;
    }

    const int j4 = lane * 4;
    float acc2[8][4];
    #pragma unroll
    for (int jj = 0; jj < 4; ++jj) {
        float bv = bn2[j4 + jj];
        #pragma unroll
        for (int ii = 0; ii < 8; ++ii) acc2[ii][jj] = bv;
    }
    for (int kt = 0; kt < 8; ++kt) {
        __syncthreads();
        {
            const float4* src = reinterpret_cast<const float4*>(Wn2 + kt * 32 * 128);
            float4* dw = reinterpret_cast<float4*>(sW);
            #pragma unroll
            for (int t0 = 0; t0 < 4; ++t0) dw[tid + t0 * 256] = src[tid + t0 * 256];
        }
        __syncthreads();
        #pragma unroll 8
        for (int kk = 0; kk < 32; ++kk) {
            float xv[8];
            #pragma unroll
            for (int ii = 0; ii < 8; ++ii) xv[ii] = sH[(nBase + ii) * 256 + kt * 32 + kk];
            float4 w = *reinterpret_cast<const float4*>(&sW[kk * 128 + j4]);
            float wv[4] = {w.x, w.y, w.z, w.w};
            #pragma unroll
            for (int ii = 0; ii < 8; ++ii)
                #pragma unroll
                for (int jj = 0; jj < 4; ++jj)
                    acc2[ii][jj] = fmaf(xv[ii], wv[jj], acc2[ii][jj]);
        }
    }
    #pragma unroll
    for (int ii = 0; ii < 8; ++ii) {
        int n = n0 + nBase + ii;
        if (n < N) {
            float4 s = *reinterpret_cast<const float4*>(&sS[(nBase + ii) * 128 + j4]);
            float4 o = make_float4(s.x + acc2[ii][0], s.y + acc2[ii][1],
                                   s.z + acc2[ii][2], s.w + acc2[ii][3]);
            *reinterpret_cast<float4*>(&out[(size_t)n * 128 + j4]) = o;
        }
    }
}

// ---------------------------------------------------------------------------
extern "C" void kernel_launch(void* const* d_in, const int* in_sizes, int n_in,
                              void* d_out, int out_size)
{
    const float* node_states = (const float*)d_in[0];
    const float* edge_feat   = (const float*)d_in[1];
    const int*   from_idx    = (const int*)d_in[2];
    const int*   to_idx      = (const int*)d_in[3];
    const float* W1  = (const float*)d_in[4];
    const float* b1  = (const float*)d_in[5];
    const float* W2  = (const float*)d_in[6];
    const float* b2  = (const float*)d_in[7];
    const float* RW1 = (const float*)d_in[8];
    const float* Rb1 = (const float*)d_in[9];
    const float* RW2 = (const float*)d_in[10];
    const float* Rb2 = (const float*)d_in[11];
    const float* Wn1 = (const float*)d_in[12];
    const float* bn1 = (const float*)d_in[13];
    const float* Wn2 = (const float*)d_in[14];
    const float* bn2 = (const float*)d_in[15];
    float* out = (float*)d_out;

    const int N = in_sizes[0] / 128;
    const int E = in_sizes[2];

    __half* w2p;
    cudaGetSymbolAddress((void**)&w2p, g_w2);

    cudaFuncSetAttribute(edge_mma_kernel, cudaFuncAttributeMaxDynamicSharedMemorySize, ESMEM);
    cudaFuncSetAttribute(precompute_y, cudaFuncAttributeMaxDynamicSharedMemorySize, 16384 * 4);
    cudaFuncSetAttribute(node_kernel, cudaFuncAttributeMaxDynamicSharedMemorySize, 49152 * 4);

    zero_agg_kernel<<<1024, 256>>>(N * 64);
    prep_w_kernel<<<256, 256>>>(W2,  w2p);
    prep_w_kernel<<<256, 256>>>(RW2, w2p + 65536);
    precompute_y<<<(N + 63) / 64, 256, 16384 * 4>>>(node_states, W1, RW1, b1, Rb1, N);
    edge_mma_kernel<<<(E + 63) / 64, 512, ESMEM>>>(
        edge_feat, from_idx, to_idx, W1, RW1, b2, Rb2, E);
    node_kernel<<<(N + 63) / 64, 256, 49152 * 4>>>(node_states, Wn1, bn1, Wn2, bn2, out, N);
}

// round 9
// speedup vs baseline: 3.4045x; 1.0735x over previous
#include <cuda_runtime.h>
#include <cuda_fp16.h>
#include <cstdint>

#define MAX_N 50000

// ---------------- device scratch (no allocation allowed) -------------------
// g_Yh row layout (1024 halfs): [Y0 | Y3 | Y1 | Y2]
//   Y0 = ns@W1_top (fwd from-side),  Y3 = ns@RW1_bot + Rb1 (rev from-side)
//   Y1 = ns@W1_bot + b1 (fwd to-side), Y2 = ns@RW1_top (rev to-side)
// fwd edge reads f-row[0:256] + t-row[512:768]; rev reads t-row[768:1024] + f-row[256:512]
__device__ __half g_Yh[(size_t)MAX_N * 1024];  // 102.4 MB, fits L2
__device__ float  g_agg[(size_t)MAX_N * 256];  // [N][256] aggregation
__device__ __half g_w2[2][65536];              // [dir][n*256+k] fp16 W2

// ---------------- small asm helpers ----------------------------------------
__device__ __forceinline__ uint32_t smem_u32(const void* p) {
    uint32_t a;
    asm("{ .reg .u64 t; cvta.to.shared.u64 t, %1; cvt.u32.u64 %0, t; }" : "=r"(a) : "l"(p));
    return a;
}
__device__ __forceinline__ void cpa16(uint32_t dst, const void* src) {
    asm volatile("cp.async.cg.shared.global [%0], [%1], 16;" :: "r"(dst), "l"(src));
}
#define CP_COMMIT() asm volatile("cp.async.commit_group;" ::: "memory")
#define CP_WAIT(n)  asm volatile("cp.async.wait_group %0;" :: "n"(n) : "memory")

__device__ __forceinline__ void ldsm4(uint32_t* r, uint32_t addr) {
    asm volatile("ldmatrix.sync.aligned.m8n8.x4.shared.b16 {%0,%1,%2,%3}, [%4];"
                 : "=r"(r[0]), "=r"(r[1]), "=r"(r[2]), "=r"(r[3]) : "r"(addr));
}
__device__ __forceinline__ void ldsm2(uint32_t* r, uint32_t addr) {
    asm volatile("ldmatrix.sync.aligned.m8n8.x2.shared.b16 {%0,%1}, [%2];"
                 : "=r"(r[0]), "=r"(r[1]) : "r"(addr));
}
__device__ __forceinline__ void mma16816(float* c, const uint32_t* a, const uint32_t* b) {
    asm volatile("mma.sync.aligned.m16n8k16.row.col.f32.f16.f16.f32 "
                 "{%0,%1,%2,%3}, {%4,%5,%6,%7}, {%8,%9}, {%0,%1,%2,%3};"
                 : "+f"(c[0]), "+f"(c[1]), "+f"(c[2]), "+f"(c[3])
                 : "r"(a[0]), "r"(a[1]), "r"(a[2]), "r"(a[3]), "r"(b[0]), "r"(b[1]));
}
__device__ __forceinline__ void red4(float* p, float x, float y, float z, float w) {
    asm volatile("red.global.add.v4.f32 [%0], {%1,%2,%3,%4};"
                 :: "l"(p), "f"(x), "f"(y), "f"(z), "f"(w) : "memory");
}
__device__ __forceinline__ float2 h2f(uint32_t u) {
    __half2 h = *reinterpret_cast<__half2*>(&u);
    return __half22float2(h);
}
__device__ __forceinline__ uint32_t f2h(float a, float b) {
    __half2 h = __floats2half2_rn(a, b);
    return *reinterpret_cast<uint32_t*>(&h);
}

// ---------------- edge-kernel smem layout (byte offsets) --------------------
#define SH    0            // [64 rows][264 halfs] hidden (stride 528B) = 33,792B
#define SWB   33792        // 2 stages x [256 n][40 halfs] = 2 x 20,480B -> 74,752
// MSG staging (fp32 [64][264]) reuses [0, 67,584) after GEMM
#define SBIAS 74752        // 256 f32
#define SWEF  75776        // 256 f32
#define SEF   76800        // 64 f32
#define ESMEM 77056

// ---------------- prep: W2 transpose + fp16 round ---------------------------
__global__ void prep_w_kernel(const float* __restrict__ W, __half* __restrict__ oh) {
    int i = blockIdx.x * 256 + threadIdx.x;      // i = n*256 + k
    if (i >= 65536) return;
    int n = i >> 8, k = i & 255;
    oh[i] = __float2half_rn(W[k * 256 + n]);
}

__global__ void zero_agg_kernel(int n4) {
    float4* p = reinterpret_cast<float4*>(g_agg);
    int i = blockIdx.x * blockDim.x + threadIdx.x;
    int stride = gridDim.x * blockDim.x;
    float4 z = make_float4(0.f, 0.f, 0.f, 0.f);
    for (; i < n4; i += stride) p[i] = z;
}

// ---------------- node-level L1 precompute (exact fp32 FFMA -> fp16) --------
__global__ __launch_bounds__(256, 1)
void precompute_y(const float* __restrict__ ns,
                  const float* __restrict__ W1, const float* __restrict__ RW1,
                  const float* __restrict__ b1, const float* __restrict__ Rb1, int N)
{
    extern __shared__ float sm[];
    float* sS = sm;           // 64*128
    float* sW = sm + 8192;    // 32*256
    const int tid = threadIdx.x;
    const int n0 = blockIdx.x * 64;

    for (int t = tid; t < 64 * 32; t += 256) {
        int n = t >> 5, c = t & 31;
        float4 v = make_float4(0.f, 0.f, 0.f, 0.f);
        if (n0 + n < N)
            v = reinterpret_cast<const float4*>(ns)[(size_t)(n0 + n) * 32 + c];
        reinterpret_cast<float4*>(sS)[t] = v;
    }

    const int wg = tid >> 5, lane = tid & 31;
    const int nb = wg * 8, j0 = lane * 8;

    for (int q = 0; q < 4; ++q) {
        const float* Wsrc = (q < 2) ? W1 : RW1;
        const int rowoff = (q & 1) * 128;
        // dest segment in packed row: q0->0 (Y0), q1->2 (Y1), q2->3 (Y2), q3->1 (Y3)
        const int seg = (q == 0) ? 0 : (q == 1) ? 2 : (q == 2) ? 3 : 1;
        float acc[8][8];
        #pragma unroll
        for (int jj = 0; jj < 8; ++jj) {
            float bv = (q == 1) ? b1[j0 + jj] : ((q == 3) ? Rb1[j0 + jj] : 0.f);
            #pragma unroll
            for (int ii = 0; ii < 8; ++ii) acc[ii][jj] = bv;
        }
        for (int kt = 0; kt < 4; ++kt) {
            __syncthreads();
            {
                const float4* src = reinterpret_cast<const float4*>(Wsrc + (rowoff + kt * 32) * 256);
                float4* dw = reinterpret_cast<float4*>(sW);
                #pragma unroll
                for (int t0 = 0; t0 < 8; ++t0) dw[tid + t0 * 256] = src[tid + t0 * 256];
            }
            __syncthreads();
            #pragma unroll 8
            for (int kk = 0; kk < 32; ++kk) {
                float xv[8];
                #pragma unroll
                for (int ii = 0; ii < 8; ++ii) xv[ii] = sS[(nb + ii) * 128 + kt * 32 + kk];
                float4 w0 = *reinterpret_cast<const float4*>(&sW[kk * 256 + j0]);
                float4 w1 = *reinterpret_cast<const float4*>(&sW[kk * 256 + j0 + 4]);
                float wv[8] = {w0.x, w0.y, w0.z, w0.w, w1.x, w1.y, w1.z, w1.w};
                #pragma unroll
                for (int ii = 0; ii < 8; ++ii)
                    #pragma unroll
                    for (int jj = 0; jj < 8; ++jj)
                        acc[ii][jj] = fmaf(xv[ii], wv[jj], acc[ii][jj]);
            }
        }
        #pragma unroll
        for (int ii = 0; ii < 8; ++ii) {
            int n = n0 + nb + ii;
            if (n < N) {
                uint4 pk;
                pk.x = f2h(acc[ii][0], acc[ii][1]);
                pk.y = f2h(acc[ii][2], acc[ii][3]);
                pk.z = f2h(acc[ii][4], acc[ii][5]);
                pk.w = f2h(acc[ii][6], acc[ii][7]);
                *reinterpret_cast<uint4*>(g_Yh + (size_t)n * 1024 + seg * 256 + j0) = pk;
            }
        }
    }
}

// ---------------- L2 GEMM: single-term fp16, cp.async double-buffered -------
__device__ __forceinline__ void gemm_l2(const __half* __restrict__ gw,
                                        uint32_t smb, int tid,
                                        uint32_t aH0, uint32_t aH1, uint32_t bB,
                                        float acc[8][4])
{
    auto copy_chunk = [&](int s, int c) {
        #pragma unroll
        for (int i = 0; i < 2; ++i) {
            int idx = i * 512 + tid;
            int n = idx >> 2, seg = idx & 3;
            const __half* src = gw + n * 256 + c * 32 + seg * 8;
            uint32_t dst = smb + SWB + (uint32_t)(s * 20480 + n * 80 + seg * 16);
            cpa16(dst, src);
        }
    };

    copy_chunk(0, 0);
    CP_COMMIT();
    for (int c = 0; c < 8; ++c) {
        const int s = c & 1;
        if (c < 7) { copy_chunk(s ^ 1, c + 1); CP_COMMIT(); CP_WAIT(1); }
        else       { CP_WAIT(0); }
        __syncthreads();
        #pragma unroll
        for (int ks = 0; ks < 2; ++ks) {
            const int step = c * 2 + ks;
            uint32_t ah = ((step < 8) ? aH0 : aH1) + (step & 7) * 32;
            uint32_t Ah[4];
            ldsm4(Ah, ah);
            const uint32_t wrow = smb + SWB + (uint32_t)(s * 20480) + bB + ks * 32;
            #pragma unroll
            for (int nf = 0; nf < 8; ++nf) {
                uint32_t Bh[2];
                ldsm2(Bh, wrow + nf * 640);
                mma16816(acc[nf], Ah, Bh);
            }
        }
        __syncthreads();
    }
}

// ---------------- edge kernel: fp16-Y combine L1 + single-term L2 ----------
__global__ __launch_bounds__(512, 2)
void edge_mma_kernel(const float* __restrict__ ef,
                     const int* __restrict__ fidx, const int* __restrict__ tidx,
                     const float* __restrict__ W1, const float* __restrict__ RW1,
                     const float* __restrict__ b2, const float* __restrict__ Rb2,
                     int E)
{
    extern __shared__ float smf[];
    char* smc = reinterpret_cast<char*>(smf);
    const uint32_t smb = smem_u32(smf);
    const int tid = threadIdx.x;
    const int wid = tid >> 5, lane = tid & 31;
    const int wm = wid & 3, wn = wid >> 2;       // 4 m-warps x 4 n-warps
    const int m0 = wm * 16, n0 = wn * 64;
    const int e0 = blockIdx.x * 64;

    float* sBias = reinterpret_cast<float*>(smc + SBIAS);
    float* sWef  = reinterpret_cast<float*>(smc + SWEF);
    float* sEf   = reinterpret_cast<float*>(smc + SEF);
    float* sMsg  = smf;                          // staging [64][264] fp32

    if (tid < 64) sEf[tid] = (e0 + tid < E) ? ef[e0 + tid] : 0.f;

    // lane-resolved fragment addresses (A from sH, stride 264 halfs)
    const int rA = (lane & 7) + ((lane >> 3) & 1) * 8;
    const int cAo = (lane >> 4) * 8;
    const uint32_t aH0 = smb + SH + (uint32_t)(((m0 + rA) * 264 + cAo) * 2);
    const uint32_t aH1 = aH0 + 256;              // +128 cols
    const uint32_t bB = (uint32_t)(((n0 + (lane & 7)) * 40 + ((lane >> 3) & 1) * 8) * 2);
    const int r0 = m0 + (lane >> 2);

    // combine-phase indices
    const int crow = tid >> 3, cq = tid & 7;
    int ce = e0 + crow; if (ce >= E) ce = E - 1;
    const int cf = fidx[ce], ct = tidx[ce];

    for (int dir = 0; dir < 2; ++dir) {
        const int* iD = dir ? fidx : tidx;       // scatter destination
        const float* bias2 = dir ? Rb2 : b2;
        const float* wef = (dir ? RW1 : W1) + 65536;    // W1 row k=256 (ef col)
        const __half* gw = g_w2[dir];

        __syncthreads();                          // prior dir's scatter reads done
        if (tid < 256) {
            sBias[tid] = bias2[tid];
            sWef[tid]  = wef[tid];
        }
        __syncthreads();

        // ---- L1 combine: h = relu(Ya + Yb + ef*wef) from fp16 g_Yh -> sH ----
        {
            const __half* Ap;
            const __half* Bp;
            if (dir == 0) {   // fwd: Y0[f] + Y1[t]
                Ap = g_Yh + (size_t)cf * 1024 + cq * 32;
                Bp = g_Yh + (size_t)ct * 1024 + 512 + cq * 32;
            } else {          // rev: Y2[t] + Y3[f]
                Ap = g_Yh + (size_t)ct * 1024 + 768 + cq * 32;
                Bp = g_Yh + (size_t)cf * 1024 + 256 + cq * 32;
            }
            const float efv = sEf[crow];
            const uint4* A4 = reinterpret_cast<const uint4*>(Ap);
            const uint4* B4 = reinterpret_cast<const uint4*>(Bp);
            #pragma unroll
            for (int i = 0; i < 4; ++i) {
                uint4 ua = A4[i], ub = B4[i];
                const int cb = cq * 32 + i * 8;
                float2 w0 = *reinterpret_cast<const float2*>(&sWef[cb]);
                float2 w1 = *reinterpret_cast<const float2*>(&sWef[cb + 2]);
                float2 w2 = *reinterpret_cast<const float2*>(&sWef[cb + 4]);
                float2 w3 = *reinterpret_cast<const float2*>(&sWef[cb + 6]);
                float2 a0 = h2f(ua.x), b0 = h2f(ub.x);
                float2 a1 = h2f(ua.y), b1v = h2f(ub.y);
                float2 a2 = h2f(ua.z), b2v = h2f(ub.z);
                float2 a3 = h2f(ua.w), b3v = h2f(ub.w);
                uint4 pk;
                pk.x = f2h(fmaxf(a0.x + b0.x + efv * w0.x, 0.f),
                           fmaxf(a0.y + b0.y + efv * w0.y, 0.f));
                pk.y = f2h(fmaxf(a1.x + b1v.x + efv * w1.x, 0.f),
                           fmaxf(a1.y + b1v.y + efv * w1.y, 0.f));
                pk.z = f2h(fmaxf(a2.x + b2v.x + efv * w2.x, 0.f),
                           fmaxf(a2.y + b2v.y + efv * w2.y, 0.f));
                pk.w = f2h(fmaxf(a3.x + b3v.x + efv * w3.x, 0.f),
                           fmaxf(a3.y + b3v.y + efv * w3.y, 0.f));
                *reinterpret_cast<uint4*>(smc + SH + (crow * 264 + cb) * 2) = pk;
            }
        }
        __syncthreads();                          // sH visible to ldmatrix

        // ---- L2: msg = h @ W2 + b2 (single-term fp16 HMMA) ------------------
        float acc[8][4];
        #pragma unroll
        for (int nf = 0; nf < 8; ++nf) {
            int cc = n0 + nf * 8 + (lane & 3) * 2;
            acc[nf][0] = sBias[cc];
            acc[nf][1] = sBias[cc + 1];
            acc[nf][2] = acc[nf][0];
            acc[nf][3] = acc[nf][1];
        }
        gemm_l2(gw, smb, tid, aH0, aH1, bB, acc);
        // gemm ends with __syncthreads: SH/SWB free for staging

        // ---- stage msg tile to smem (fp32), then cooperative v4 scatter -----
        #pragma unroll
        for (int nf = 0; nf < 8; ++nf) {
            int cc = n0 + nf * 8 + (lane & 3) * 2;
            *reinterpret_cast<float2*>(&sMsg[r0 * 264 + cc]) =
                make_float2(acc[nf][0], acc[nf][1]);
            *reinterpret_cast<float2*>(&sMsg[(r0 + 8) * 264 + cc]) =
                make_float2(acc[nf][2], acc[nf][3]);
        }
        __syncthreads();
        {
            const int e2 = e0 + crow;            // crow = tid>>3, cq = tid&7
            if (e2 < E) {
                float* dst = g_agg + (size_t)iD[e2] * 256 + cq * 32;
                const float* src = sMsg + crow * 264 + cq * 32;
                #pragma unroll
                for (int i = 0; i < 8; ++i)
                    red4(dst + i * 4, src[i * 4], src[i * 4 + 1],
                         src[i * 4 + 2], src[i * 4 + 3]);
            }
        }
    }
}

// ---------------- node update MLP + residual (FFMA, proven) ----------------
__global__ __launch_bounds__(256, 1)
void node_kernel(const float* __restrict__ node_states,
                 const float* __restrict__ Wn1, const float* __restrict__ bn1,
                 const float* __restrict__ Wn2, const float* __restrict__ bn2,
                 float* __restrict__ out, int N)
{
    extern __shared__ float sm[];
    float* sA = sm;            // 64*256
    float* sS = sm + 16384;    // 64*128
    float* sH = sm + 24576;    // 64*256
    float* sW = sm + 40960;    // 32*256

    const int tid = threadIdx.x;
    const int n0  = blockIdx.x * 64;

    for (int t = tid; t < 64 * 64; t += 256) {
        int n = t >> 6, c = t & 63;
        float4 v = make_float4(0.f, 0.f, 0.f, 0.f);
        if (n0 + n < N)
            v = reinterpret_cast<const float4*>(g_agg)[(size_t)(n0 + n) * 64 + c];
        reinterpret_cast<float4*>(sA)[t] = v;
    }
    for (int t = tid; t < 64 * 32; t += 256) {
        int n = t >> 5, c = t & 31;
        float4 v = make_float4(0.f, 0.f, 0.f, 0.f);
        if (n0 + n < N)
            v = reinterpret_cast<const float4*>(node_states)[(size_t)(n0 + n) * 32 + c];
        reinterpret_cast<float4*>(sS)[t] = v;
    }
    __syncthreads();

    const int wg = tid >> 5, lane = tid & 31;
    const int nBase = wg * 8, j0 = lane * 8;

    float acc[8][8];
    #pragma unroll
    for (int jj = 0; jj < 8; ++jj) {
        float bv = bn1[j0 + jj];
        #pragma unroll
        for (int ii = 0; ii < 8; ++ii) acc[ii][jj] = bv;
    }
    for (int kt = 0; kt < 12; ++kt) {
        __syncthreads();
        {
            const float4* src = reinterpret_cast<const float4*>(Wn1 + kt * 32 * 256);
            float4* dw = reinterpret_cast<float4*>(sW);
            #pragma unroll
            for (int t0 = 0; t0 < 8; ++t0) dw[tid + t0 * 256] = src[tid + t0 * 256];
        }
        __syncthreads();
        const float* Xb; int strd;
        if (kt < 8) { Xb = sA + kt * 32;       strd = 256; }
        else        { Xb = sS + (kt - 8) * 32; strd = 128; }
        #pragma unroll 8
        for (int kk = 0; kk < 32; ++kk) {
            float xv[8];
            #pragma unroll
            for (int ii = 0; ii < 8; ++ii) xv[ii] = Xb[(nBase + ii) * strd + kk];
            float4 w0 = *reinterpret_cast<const float4*>(&sW[kk * 256 + j0]);
            float4 w1 = *reinterpret_cast<const float4*>(&sW[kk * 256 + j0 + 4]);
            float wv[8] = {w0.x, w0.y, w0.z, w0.w, w1.x, w1.y, w1.z, w1.w};
            #pragma unroll
            for (int ii = 0; ii < 8; ++ii)
                #pragma unroll
                for (int jj = 0; jj < 8; ++jj)
                    acc[ii][jj] = fmaf(xv[ii], wv[jj], acc[ii][jj]);
        }
    }
    #pragma unroll
    for (int ii = 0; ii < 8; ++ii) {
        float4 h0 = make_float4(fmaxf(acc[ii][0], 0.f), fmaxf(acc[ii][1], 0.f),
                                fmaxf(acc[ii][2], 0.f), fmaxf(acc[ii][3], 0.f));
        float4 h1 = make_float4(fmaxf(acc[ii][4], 0.f), fmaxf(acc[ii][5], 0.f),
                                fmaxf(acc[ii][6], 0.f), fmaxf(acc[ii][7], 0.f));
        *reinterpret_cast<float4*>(&sH[(nBase + ii) * 256 + j0])     = h0;
        *reinterpret_cast<float4*>(&sH[(nBase + ii) * 256 + j0 + 4]) = h1;
    }

    const int j4 = lane * 4;
    float acc2[8][4];
    #pragma unroll
    for (int jj = 0; jj < 4; ++jj) {
        float bv = bn2[j4 + jj];
        #pragma unroll
        for (int ii = 0; ii < 8; ++ii) acc2[ii][jj] = bv;
    }
    for (int kt = 0; kt < 8; ++kt) {
        __syncthreads();
        {
            const float4* src = reinterpret_cast<const float4*>(Wn2 + kt * 32 * 128);
            float4* dw = reinterpret_cast<float4*>(sW);
            #pragma unroll
            for (int t0 = 0; t0 < 4; ++t0) dw[tid + t0 * 256] = src[tid + t0 * 256];
        }
        __syncthreads();
        #pragma unroll 8
        for (int kk = 0; kk < 32; ++kk) {
            float xv[8];
            #pragma unroll
            for (int ii = 0; ii < 8; ++ii) xv[ii] = sH[(nBase + ii) * 256 + kt * 32 + kk];
            float4 w = *reinterpret_cast<const float4*>(&sW[kk * 128 + j4]);
            float wv[4] = {w.x, w.y, w.z, w.w};
            #pragma unroll
            for (int ii = 0; ii < 8; ++ii)
                #pragma unroll
                for (int jj = 0; jj < 4; ++jj)
                    acc2[ii][jj] = fmaf(xv[ii], wv[jj], acc2[ii][jj]);
        }
    }
    #pragma unroll
    for (int ii = 0; ii < 8; ++ii) {
        int n = n0 + nBase + ii;
        if (n < N) {
            float4 s = *reinterpret_cast<const float4*>(&sS[(nBase + ii) * 128 + j4]);
            float4 o = make_float4(s.x + acc2[ii][0], s.y + acc2[ii][1],
                                   s.z + acc2[ii][2], s.w + acc2[ii][3]);
            *reinterpret_cast<float4*>(&out[(size_t)n * 128 + j4]) = o;
        }
    }
}

// ---------------------------------------------------------------------------
extern "C" void kernel_launch(void* const* d_in, const int* in_sizes, int n_in,
                              void* d_out, int out_size)
{
    const float* node_states = (const float*)d_in[0];
    const float* edge_feat   = (const float*)d_in[1];
    const int*   from_idx    = (const int*)d_in[2];
    const int*   to_idx      = (const int*)d_in[3];
    const float* W1  = (const float*)d_in[4];
    const float* b1  = (const float*)d_in[5];
    const float* W2  = (const float*)d_in[6];
    const float* b2  = (const float*)d_in[7];
    const float* RW1 = (const float*)d_in[8];
    const float* Rb1 = (const float*)d_in[9];
    const float* RW2 = (const float*)d_in[10];
    const float* Rb2 = (const float*)d_in[11];
    const float* Wn1 = (const float*)d_in[12];
    const float* bn1 = (const float*)d_in[13];
    const float* Wn2 = (const float*)d_in[14];
    const float* bn2 = (const float*)d_in[15];
    float* out = (float*)d_out;

    const int N = in_sizes[0] / 128;
    const int E = in_sizes[2];

    __half* w2p;
    cudaGetSymbolAddress((void**)&w2p, g_w2);

    cudaFuncSetAttribute(edge_mma_kernel, cudaFuncAttributeMaxDynamicSharedMemorySize, ESMEM);
    cudaFuncSetAttribute(precompute_y, cudaFuncAttributeMaxDynamicSharedMemorySize, 16384 * 4);
    cudaFuncSetAttribute(node_kernel, cudaFuncAttributeMaxDynamicSharedMemorySize, 49152 * 4);

    zero_agg_kernel<<<1024, 256>>>(N * 64);
    prep_w_kernel<<<256, 256>>>(W2,  w2p);
    prep_w_kernel<<<256, 256>>>(RW2, w2p + 65536);
    precompute_y<<<(N + 63) / 64, 256, 16384 * 4>>>(node_states, W1, RW1, b1, Rb1, N);
    edge_mma_kernel<<<(E + 63) / 64, 512, ESMEM>>>(
        edge_feat, from_idx, to_idx, W1, RW1, b2, Rb2, E);
    node_kernel<<<(N + 63) / 64, 256, 49152 * 4>>>(node_states, Wn1, bn1, Wn2, bn2, out, N);
}

// round 10
// speedup vs baseline: 3.9228x; 1.1522x over previous
#include <cuda_runtime.h>
#include <cuda_fp16.h>
#include <cstdint>

#define MAX_N 50000

// ---------------- device scratch (no allocation allowed) -------------------
// g_Yh row layout (1024 halfs): [Y0 | Y3 | Y1 | Y2]
//   Y0 = ns@W1_top (fwd from-side),  Y3 = ns@RW1_bot + Rb1 (rev from-side)
//   Y1 = ns@W1_bot + b1 (fwd to-side), Y2 = ns@RW1_top (rev to-side)
// fwd edge reads f-row[0:256] + t-row[512:768]; rev reads t-row[768:1024] + f-row[256:512]
__device__ __half g_Yh[(size_t)MAX_N * 1024];  // 102.4 MB, fits L2
__device__ float  g_agg[(size_t)MAX_N * 256];  // [N][256] aggregation
__device__ __half g_w2[2][65536];              // [dir][n*256+k] fp16 W2

// ---------------- small asm helpers ----------------------------------------
__device__ __forceinline__ uint32_t smem_u32(const void* p) {
    uint32_t a;
    asm("{ .reg .u64 t; cvta.to.shared.u64 t, %1; cvt.u32.u64 %0, t; }" : "=r"(a) : "l"(p));
    return a;
}
__device__ __forceinline__ void cpa16(uint32_t dst, const void* src) {
    asm volatile("cp.async.cg.shared.global [%0], [%1], 16;" :: "r"(dst), "l"(src));
}
#define CP_COMMIT() asm volatile("cp.async.commit_group;" ::: "memory")
#define CP_WAIT(n)  asm volatile("cp.async.wait_group %0;" :: "n"(n) : "memory")

__device__ __forceinline__ void ldsm4(uint32_t* r, uint32_t addr) {
    asm volatile("ldmatrix.sync.aligned.m8n8.x4.shared.b16 {%0,%1,%2,%3}, [%4];"
                 : "=r"(r[0]), "=r"(r[1]), "=r"(r[2]), "=r"(r[3]) : "r"(addr));
}
__device__ __forceinline__ void ldsm2(uint32_t* r, uint32_t addr) {
    asm volatile("ldmatrix.sync.aligned.m8n8.x2.shared.b16 {%0,%1}, [%2];"
                 : "=r"(r[0]), "=r"(r[1]) : "r"(addr));
}
__device__ __forceinline__ void mma16816(float* c, const uint32_t* a, const uint32_t* b) {
    asm volatile("mma.sync.aligned.m16n8k16.row.col.f32.f16.f16.f32 "
                 "{%0,%1,%2,%3}, {%4,%5,%6,%7}, {%8,%9}, {%0,%1,%2,%3};"
                 : "+f"(c[0]), "+f"(c[1]), "+f"(c[2]), "+f"(c[3])
                 : "r"(a[0]), "r"(a[1]), "r"(a[2]), "r"(a[3]), "r"(b[0]), "r"(b[1]));
}
__device__ __forceinline__ void red2(float* p, float x, float y) {
    asm volatile("red.global.add.v2.f32 [%0], {%1,%2};" :: "l"(p), "f"(x), "f"(y) : "memory");
}
__device__ __forceinline__ float2 h2f(uint32_t u) {
    __half2 h = *reinterpret_cast<__half2*>(&u);
    return __half22float2(h);
}
__device__ __forceinline__ uint32_t f2h(float a, float b) {
    __half2 h = __floats2half2_rn(a, b);
    return *reinterpret_cast<uint32_t*>(&h);
}

// ---------------- edge-kernel smem layout (byte offsets) --------------------
#define SH    0            // [128 rows][264 halfs] hidden (stride 528B) = 67,584B
#define SWB   67584        // 2 stages x [256 n][40 halfs] = 2 x 20,480B -> 108,544
#define SBIAS 108544       // 256 f32
#define SWEF  109568       // 256 f32
#define SEF   110592       // 128 f32
#define ESMEM 111104

// ---------------- prep: W2 transpose + fp16 round ---------------------------
__global__ void prep_w_kernel(const float* __restrict__ W, __half* __restrict__ oh) {
    int i = blockIdx.x * 256 + threadIdx.x;      // i = n*256 + k
    if (i >= 65536) return;
    int n = i >> 8, k = i & 255;
    oh[i] = __float2half_rn(W[k * 256 + n]);
}

__global__ void zero_agg_kernel(int n4) {
    float4* p = reinterpret_cast<float4*>(g_agg);
    int i = blockIdx.x * blockDim.x + threadIdx.x;
    int stride = gridDim.x * blockDim.x;
    float4 z = make_float4(0.f, 0.f, 0.f, 0.f);
    for (; i < n4; i += stride) p[i] = z;
}

// ---------------- node-level L1 precompute (exact fp32 FFMA -> fp16) --------
__global__ __launch_bounds__(256, 1)
void precompute_y(const float* __restrict__ ns,
                  const float* __restrict__ W1, const float* __restrict__ RW1,
                  const float* __restrict__ b1, const float* __restrict__ Rb1, int N)
{
    extern __shared__ float sm[];
    float* sS = sm;           // 64*128
    float* sW = sm + 8192;    // 32*256
    const int tid = threadIdx.x;
    const int n0 = blockIdx.x * 64;

    for (int t = tid; t < 64 * 32; t += 256) {
        int n = t >> 5, c = t & 31;
        float4 v = make_float4(0.f, 0.f, 0.f, 0.f);
        if (n0 + n < N)
            v = reinterpret_cast<const float4*>(ns)[(size_t)(n0 + n) * 32 + c];
        reinterpret_cast<float4*>(sS)[t] = v;
    }

    const int wg = tid >> 5, lane = tid & 31;
    const int nb = wg * 8, j0 = lane * 8;

    for (int q = 0; q < 4; ++q) {
        const float* Wsrc = (q < 2) ? W1 : RW1;
        const int rowoff = (q & 1) * 128;
        // dest segment in packed row: q0->0 (Y0), q1->2 (Y1), q2->3 (Y2), q3->1 (Y3)
        const int seg = (q == 0) ? 0 : (q == 1) ? 2 : (q == 2) ? 3 : 1;
        float acc[8][8];
        #pragma unroll
        for (int jj = 0; jj < 8; ++jj) {
            float bv = (q == 1) ? b1[j0 + jj] : ((q == 3) ? Rb1[j0 + jj] : 0.f);
            #pragma unroll
            for (int ii = 0; ii < 8; ++ii) acc[ii][jj] = bv;
        }
        for (int kt = 0; kt < 4; ++kt) {
            __syncthreads();
            {
                const float4* src = reinterpret_cast<const float4*>(Wsrc + (rowoff + kt * 32) * 256);
                float4* dw = reinterpret_cast<float4*>(sW);
                #pragma unroll
                for (int t0 = 0; t0 < 8; ++t0) dw[tid + t0 * 256] = src[tid + t0 * 256];
            }
            __syncthreads();
            #pragma unroll 8
            for (int kk = 0; kk < 32; ++kk) {
                float xv[8];
                #pragma unroll
                for (int ii = 0; ii < 8; ++ii) xv[ii] = sS[(nb + ii) * 128 + kt * 32 + kk];
                float4 w0 = *reinterpret_cast<const float4*>(&sW[kk * 256 + j0]);
                float4 w1 = *reinterpret_cast<const float4*>(&sW[kk * 256 + j0 + 4]);
                float wv[8] = {w0.x, w0.y, w0.z, w0.w, w1.x, w1.y, w1.z, w1.w};
                #pragma unroll
                for (int ii = 0; ii < 8; ++ii)
                    #pragma unroll
                    for (int jj = 0; jj < 8; ++jj)
                        acc[ii][jj] = fmaf(xv[ii], wv[jj], acc[ii][jj]);
            }
        }
        #pragma unroll
        for (int ii = 0; ii < 8; ++ii) {
            int n = n0 + nb + ii;
            if (n < N) {
                uint4 pk;
                pk.x = f2h(acc[ii][0], acc[ii][1]);
                pk.y = f2h(acc[ii][2], acc[ii][3]);
                pk.z = f2h(acc[ii][4], acc[ii][5]);
                pk.w = f2h(acc[ii][6], acc[ii][7]);
                *reinterpret_cast<uint4*>(g_Yh + (size_t)n * 1024 + seg * 256 + j0) = pk;
            }
        }
    }
}

// ---------------- L2 GEMM: single-term fp16, M=128, warp tile 32x64 ---------
__device__ __forceinline__ void gemm_l2(const __half* __restrict__ gw,
                                        uint32_t smb, int tid,
                                        uint32_t aB0, uint32_t aB1, uint32_t bB,
                                        float acc0[8][4], float acc1[8][4])
{
    auto copy_chunk = [&](int s, int c) {
        #pragma unroll
        for (int i = 0; i < 2; ++i) {
            int idx = i * 512 + tid;
            int n = idx >> 2, seg = idx & 3;
            const __half* src = gw + n * 256 + c * 32 + seg * 8;
            uint32_t dst = smb + SWB + (uint32_t)(s * 20480 + n * 80 + seg * 16);
            cpa16(dst, src);
        }
    };

    copy_chunk(0, 0);
    CP_COMMIT();
    for (int c = 0; c < 8; ++c) {
        const int s = c & 1;
        if (c < 7) { copy_chunk(s ^ 1, c + 1); CP_COMMIT(); CP_WAIT(1); }
        else       { CP_WAIT(0); }
        __syncthreads();
        #pragma unroll
        for (int ks = 0; ks < 2; ++ks) {
            const int step = c * 2 + ks;
            const uint32_t coloff = ((step < 8) ? 0u : 256u) + (step & 7) * 32;
            uint32_t A0[4], A1[4];
            ldsm4(A0, aB0 + coloff);
            ldsm4(A1, aB1 + coloff);
            const uint32_t wrow = smb + SWB + (uint32_t)(s * 20480) + bB + ks * 32;
            #pragma unroll
            for (int nf = 0; nf < 8; ++nf) {
                uint32_t Bh[2];
                ldsm2(Bh, wrow + nf * 640);
                mma16816(acc0[nf], A0, Bh);
                mma16816(acc1[nf], A1, Bh);
            }
        }
        __syncthreads();
    }
}

// ---------------- edge kernel: 128 edges/CTA, fp16-Y combine + L2 MMA ------
__global__ __launch_bounds__(512, 1)
void edge_mma_kernel(const float* __restrict__ ef,
                     const int* __restrict__ fidx, const int* __restrict__ tidx,
                     const float* __restrict__ W1, const float* __restrict__ RW1,
                     const float* __restrict__ b2, const float* __restrict__ Rb2,
                     int E)
{
    extern __shared__ float smf[];
    char* smc = reinterpret_cast<char*>(smf);
    const uint32_t smb = smem_u32(smf);
    const int tid = threadIdx.x;
    const int wid = tid >> 5, lane = tid & 31;
    const int wm = wid & 3, wn = wid >> 2;       // 4 m-warps x 4 n-warps
    const int m0 = wm * 32, n0 = wn * 64;        // warp tile 32 x 64
    const int e0 = blockIdx.x * 128;

    float* sBias = reinterpret_cast<float*>(smc + SBIAS);
    float* sWef  = reinterpret_cast<float*>(smc + SWEF);
    float* sEf   = reinterpret_cast<float*>(smc + SEF);

    if (tid < 128) sEf[tid] = (e0 + tid < E) ? ef[e0 + tid] : 0.f;

    // lane-resolved fragment addresses (A from sH, stride 264 halfs)
    const int rA = (lane & 7) + ((lane >> 3) & 1) * 8;
    const int cAo = (lane >> 4) * 8;
    const uint32_t aB0 = smb + SH + (uint32_t)(((m0 + rA) * 264 + cAo) * 2);
    const uint32_t aB1 = aB0 + 16 * 528;         // +16 rows
    const uint32_t bB = (uint32_t)(((n0 + (lane & 7)) * 40 + ((lane >> 3) & 1) * 8) * 2);
    const int r0 = m0 + (lane >> 2);

    // combine-phase indices: 128 rows x 4 col-quarters (64 halfs each)
    const int crow = tid >> 2, cq = tid & 3;
    int ce = e0 + crow; if (ce >= E) ce = E - 1;
    const int cf = fidx[ce], ct = tidx[ce];

    for (int dir = 0; dir < 2; ++dir) {
        const int* iD = dir ? fidx : tidx;       // scatter destination
        const float* bias2 = dir ? Rb2 : b2;
        const float* wef = (dir ? RW1 : W1) + 65536;    // W1 row k=256 (ef col)
        const __half* gw = g_w2[dir];

        __syncthreads();                          // prior dir's smem readers done
        if (tid < 256) {
            sBias[tid] = bias2[tid];
            sWef[tid]  = wef[tid];
        }
        __syncthreads();

        // ---- L1 combine: h = relu(Ya + Yb + ef*wef) from fp16 g_Yh -> sH ----
        {
            const __half* Ap;
            const __half* Bp;
            if (dir == 0) {   // fwd: Y0[f] + Y1[t]
                Ap = g_Yh + (size_t)cf * 1024 + cq * 64;
                Bp = g_Yh + (size_t)ct * 1024 + 512 + cq * 64;
            } else {          // rev: Y2[t] + Y3[f]
                Ap = g_Yh + (size_t)ct * 1024 + 768 + cq * 64;
                Bp = g_Yh + (size_t)cf * 1024 + 256 + cq * 64;
            }
            const float efv = sEf[crow];
            const uint4* A4 = reinterpret_cast<const uint4*>(Ap);
            const uint4* B4 = reinterpret_cast<const uint4*>(Bp);
            #pragma unroll
            for (int i = 0; i < 8; ++i) {
                uint4 ua = A4[i], ub = B4[i];
                const int cb = cq * 64 + i * 8;
                float2 w0 = *reinterpret_cast<const float2*>(&sWef[cb]);
                float2 w1 = *reinterpret_cast<const float2*>(&sWef[cb + 2]);
                float2 w2 = *reinterpret_cast<const float2*>(&sWef[cb + 4]);
                float2 w3 = *reinterpret_cast<const float2*>(&sWef[cb + 6]);
                float2 a0 = h2f(ua.x), b0 = h2f(ub.x);
                float2 a1 = h2f(ua.y), b1v = h2f(ub.y);
                float2 a2 = h2f(ua.z), b2v = h2f(ub.z);
                float2 a3 = h2f(ua.w), b3v = h2f(ub.w);
                uint4 pk;
                pk.x = f2h(fmaxf(a0.x + b0.x + efv * w0.x, 0.f),
                           fmaxf(a0.y + b0.y + efv * w0.y, 0.f));
                pk.y = f2h(fmaxf(a1.x + b1v.x + efv * w1.x, 0.f),
                           fmaxf(a1.y + b1v.y + efv * w1.y, 0.f));
                pk.z = f2h(fmaxf(a2.x + b2v.x + efv * w2.x, 0.f),
                           fmaxf(a2.y + b2v.y + efv * w2.y, 0.f));
                pk.w = f2h(fmaxf(a3.x + b3v.x + efv * w3.x, 0.f),
                           fmaxf(a3.y + b3v.y + efv * w3.y, 0.f));
                *reinterpret_cast<uint4*>(smc + SH + (crow * 264 + cb) * 2) = pk;
            }
        }
        __syncthreads();                          // sH visible to ldmatrix

        // ---- L2: msg = h @ W2 + b2 (single-term fp16 HMMA) ------------------
        float acc0[8][4], acc1[8][4];
        #pragma unroll
        for (int nf = 0; nf < 8; ++nf) {
            int cc = n0 + nf * 8 + (lane & 3) * 2;
            float bv0 = sBias[cc], bv1 = sBias[cc + 1];
            acc0[nf][0] = bv0; acc0[nf][1] = bv1;
            acc0[nf][2] = bv0; acc0[nf][3] = bv1;
            acc1[nf][0] = bv0; acc1[nf][1] = bv1;
            acc1[nf][2] = bv0; acc1[nf][3] = bv1;
        }
        gemm_l2(gw, smb, tid, aB0, aB1, bB, acc0, acc1);

        // ---- scatter: red.v2 straight from accumulators ---------------------
        {
            const int e00 = e0 + r0;
            const int e08 = e00 + 8, e16 = e00 + 16, e24 = e00 + 24;
            const int d00 = (e00 < E) ? iD[e00] : 0;
            const int d08 = (e08 < E) ? iD[e08] : 0;
            const int d16 = (e16 < E) ? iD[e16] : 0;
            const int d24 = (e24 < E) ? iD[e24] : 0;
            float* p00 = g_agg + (size_t)d00 * 256;
            float* p08 = g_agg + (size_t)d08 * 256;
            float* p16 = g_agg + (size_t)d16 * 256;
            float* p24 = g_agg + (size_t)d24 * 256;
            #pragma unroll
            for (int nf = 0; nf < 8; ++nf) {
                int cc = n0 + nf * 8 + (lane & 3) * 2;
                if (e00 < E) red2(p00 + cc, acc0[nf][0], acc0[nf][1]);
                if (e08 < E) red2(p08 + cc, acc0[nf][2], acc0[nf][3]);
                if (e16 < E) red2(p16 + cc, acc1[nf][0], acc1[nf][1]);
                if (e24 < E) red2(p24 + cc, acc1[nf][2], acc1[nf][3]);
            }
        }
    }
}

// ---------------- node update MLP + residual (FFMA, proven) ----------------
__global__ __launch_bounds__(256, 1)
void node_kernel(const float* __restrict__ node_states,
                 const float* __restrict__ Wn1, const float* __restrict__ bn1,
                 const float* __restrict__ Wn2, const float* __restrict__ bn2,
                 float* __restrict__ out, int N)
{
    extern __shared__ float sm[];
    float* sA = sm;            // 64*256
    float* sS = sm + 16384;    // 64*128
    float* sH = sm + 24576;    // 64*256
    float* sW = sm + 40960;    // 32*256

    const int tid = threadIdx.x;
    const int n0  = blockIdx.x * 64;

    for (int t = tid; t < 64 * 64; t += 256) {
        int n = t >> 6, c = t & 63;
        float4 v = make_float4(0.f, 0.f, 0.f, 0.f);
        if (n0 + n < N)
            v = reinterpret_cast<const float4*>(g_agg)[(size_t)(n0 + n) * 64 + c];
        reinterpret_cast<float4*>(sA)[t] = v;
    }
    for (int t = tid; t < 64 * 32; t += 256) {
        int n = t >> 5, c = t & 31;
        float4 v = make_float4(0.f, 0.f, 0.f, 0.f);
        if (n0 + n < N)
            v = reinterpret_cast<const float4*>(node_states)[(size_t)(n0 + n) * 32 + c];
        reinterpret_cast<float4*>(sS)[t] = v;
    }
    __syncthreads();

    const int wg = tid >> 5, lane = tid & 31;
    const int nBase = wg * 8, j0 = lane * 8;

    float acc[8][8];
    #pragma unroll
    for (int jj = 0; jj < 8; ++jj) {
        float bv = bn1[j0 + jj];
        #pragma unroll
        for (int ii = 0; ii < 8; ++ii) acc[ii][jj] = bv;
    }
    for (int kt = 0; kt < 12; ++kt) {
        __syncthreads();
        {
            const float4* src = reinterpret_cast<const float4*>(Wn1 + kt * 32 * 256);
            float4* dw = reinterpret_cast<float4*>(sW);
            #pragma unroll
            for (int t0 = 0; t0 < 8; ++t0) dw[tid + t0 * 256] = src[tid + t0 * 256];
        }
        __syncthreads();
        const float* Xb; int strd;
        if (kt < 8) { Xb = sA + kt * 32;       strd = 256; }
        else        { Xb = sS + (kt - 8) * 32; strd = 128; }
        #pragma unroll 8
        for (int kk = 0; kk < 32; ++kk) {
            float xv[8];
            #pragma unroll
            for (int ii = 0; ii < 8; ++ii) xv[ii] = Xb[(nBase + ii) * strd + kk];
            float4 w0 = *reinterpret_cast<const float4*>(&sW[kk * 256 + j0]);
            float4 w1 = *reinterpret_cast<const float4*>(&sW[kk * 256 + j0 + 4]);
            float wv[8] = {w0.x, w0.y, w0.z, w0.w, w1.x, w1.y, w1.z, w1.w};
            #pragma unroll
            for (int ii = 0; ii < 8; ++ii)
                #pragma unroll
                for (int jj = 0; jj < 8; ++jj)
                    acc[ii][jj] = fmaf(xv[ii], wv[jj], acc[ii][jj]);
        }
    }
    #pragma unroll
    for (int ii = 0; ii < 8; ++ii) {
        float4 h0 = make_float4(fmaxf(acc[ii][0], 0.f), fmaxf(acc[ii][1], 0.f),
                                fmaxf(acc[ii][2], 0.f), fmaxf(acc[ii][3], 0.f));
        float4 h1 = make_float4(fmaxf(acc[ii][4], 0.f), fmaxf(acc[ii][5], 0.f),
                                fmaxf(acc[ii][6], 0.f), fmaxf(acc[ii][7], 0.f));
        *reinterpret_cast<float4*>(&sH[(nBase + ii) * 256 + j0])     = h0;
        *reinterpret_cast<float4*>(&sH[(nBase + ii) * 256 + j0 + 4]) = h1;
    }

    const int j4 = lane * 4;
    float acc2[8][4];
    #pragma unroll
    for (int jj = 0; jj < 4; ++jj) {
        float bv = bn2[j4 + jj];
        #pragma unroll
        for (int ii = 0; ii < 8; ++ii) acc2[ii][jj] = bv;
    }
    for (int kt = 0; kt < 8; ++kt) {
        __syncthreads();
        {
            const float4* src = reinterpret_cast<const float4*>(Wn2 + kt * 32 * 128);
            float4* dw = reinterpret_cast<float4*>(sW);
            #pragma unroll
            for (int t0 = 0; t0 < 4; ++t0) dw[tid + t0 * 256] = src[tid + t0 * 256];
        }
        __syncthreads();
        #pragma unroll 8
        for (int kk = 0; kk < 32; ++kk) {
            float xv[8];
            #pragma unroll
            for (int ii = 0; ii < 8; ++ii) xv[ii] = sH[(nBase + ii) * 256 + kt * 32 + kk];
            float4 w = *reinterpret_cast<const float4*>(&sW[kk * 128 + j4]);
            float wv[4] = {w.x, w.y, w.z, w.w};
            #pragma unroll
            for (int ii = 0; ii < 8; ++ii)
                #pragma unroll
                for (int jj = 0; jj < 4; ++jj)
                    acc2[ii][jj] = fmaf(xv[ii], wv[jj], acc2[ii][jj]);
        }
    }
    #pragma unroll
    for (int ii = 0; ii < 8; ++ii) {
        int n = n0 + nBase + ii;
        if (n < N) {
            float4 s = *reinterpret_cast<const float4*>(&sS[(nBase + ii) * 128 + j4]);
            float4 o = make_float4(s.x + acc2[ii][0], s.y + acc2[ii][1],
                                   s.z + acc2[ii][2], s.w + acc2[ii][3]);
            *reinterpret_cast<float4*>(&out[(size_t)n * 128 + j4]) = o;
        }
    }
}

// ---------------------------------------------------------------------------
extern "C" void kernel_launch(void* const* d_in, const int* in_sizes, int n_in,
                              void* d_out, int out_size)
{
    const float* node_states = (const float*)d_in[0];
    const float* edge_feat   = (const float*)d_in[1];
    const int*   from_idx    = (const int*)d_in[2];
    const int*   to_idx      = (const int*)d_in[3];
    const float* W1  = (const float*)d_in[4];
    const float* b1  = (const float*)d_in[5];
    const float* W2  = (const float*)d_in[6];
    const float* b2  = (const float*)d_in[7];
    const float* RW1 = (const float*)d_in[8];
    const float* Rb1 = (const float*)d_in[9];
    const float* RW2 = (const float*)d_in[10];
    const float* Rb2 = (const float*)d_in[11];
    const float* Wn1 = (const float*)d_in[12];
    const float* bn1 = (const float*)d_in[13];
    const float* Wn2 = (const float*)d_in[14];
    const float* bn2 = (const float*)d_in[15];
    float* out = (float*)d_out;

    const int N = in_sizes[0] / 128;
    const int E = in_sizes[2];

    __half* w2p;
    cudaGetSymbolAddress((void**)&w2p, g_w2);

    cudaFuncSetAttribute(edge_mma_kernel, cudaFuncAttributeMaxDynamicSharedMemorySize, ESMEM);
    cudaFuncSetAttribute(precompute_y, cudaFuncAttributeMaxDynamicSharedMemorySize, 16384 * 4);
    cudaFuncSetAttribute(node_kernel, cudaFuncAttributeMaxDynamicSharedMemorySize, 49152 * 4);

    zero_agg_kernel<<<1024, 256>>>(N * 64);
    prep_w_kernel<<<256, 256>>>(W2,  w2p);
    prep_w_kernel<<<256, 256>>>(RW2, w2p + 65536);
    precompute_y<<<(N + 63) / 64, 256, 16384 * 4>>>(node_states, W1, RW1, b1, Rb1, N);
    edge_mma_kernel<<<(E + 127) / 128, 512, ESMEM>>>(
        edge_feat, from_idx, to_idx, W1, RW1, b2, Rb2, E);
    node_kernel<<<(N + 63) / 64, 256, 49152 * 4>>>(node_states, Wn1, bn1, Wn2, bn2, out, N);
}